// round 1
// baseline (speedup 1.0000x reference)
#include <cuda_runtime.h>

#define H 128
#define DEI 257      // 2H+1
#define NMAX 50000
#define TE 16        // edges per block
#define TN 8         // nodes per block

// Scratch accumulators (no dynamic allocation allowed)
__device__ float g_agg[NMAX * H];   // segment_sum(ef) by row
__device__ float g_dx[NMAX * 3];    // segment_sum(rel*gate) by row
__device__ float g_cnt[NMAX];       // segment counts

__device__ __forceinline__ float silu(float v) {
    return v / (1.0f + __expf(-v));
}

__global__ void zero_kernel(int n) {
    int total = n * H + n * 3 + n;
    for (int i = blockIdx.x * blockDim.x + threadIdx.x; i < total;
         i += gridDim.x * blockDim.x) {
        if (i < n * H) g_agg[i] = 0.0f;
        else if (i < n * H + n * 3) g_dx[i - n * H] = 0.0f;
        else g_cnt[i - n * H - n * 3] = 0.0f;
    }
}

// ---------------------------------------------------------------------------
// Edge kernel: for a tile of TE edges, compute
//   ein = [h[row], h[col], dist2]                  (257)
//   f1  = silu(ein @ We1 + be1)                    (128)
//   f2  = silu(f1 @ We2 + be2)                     (128)   == ef
//   g1  = silu(f2 @ Wc1 + bc1)                     (128)
//   gate= g1 @ Wc2 + bc2                           (1)
// then atomically scatter: agg[row] += f2, dx[row] += rel*gate, cnt[row] += 1
// 128 threads: thread j owns output column j; TE edges in register accums.
// ---------------------------------------------------------------------------
__global__ __launch_bounds__(128) void edge_kernel(
    const float* __restrict__ x, const float* __restrict__ h,
    const int* __restrict__ ei, int E, int n,
    const float* __restrict__ We1, const float* __restrict__ be1,
    const float* __restrict__ We2, const float* __restrict__ be2,
    const float* __restrict__ Wc1, const float* __restrict__ bc1,
    const float* __restrict__ Wc2, const float* __restrict__ bc2)
{
    __shared__ float s_ein[TE][260];   // 257 padded to 260 (keeps float4 align)
    __shared__ float s_f1[TE][H];
    __shared__ float s_f2[TE][H];
    __shared__ float s_g[TE][H];
    __shared__ float s_rel[TE][3];
    __shared__ int   s_row[TE];
    __shared__ float s_gate[TE];
    __shared__ float s_wc2[H];

    const int j = threadIdx.x;
    const int e0 = blockIdx.x * TE;

    s_wc2[j] = Wc2[j];

    // Stage edge inputs
    #pragma unroll
    for (int e = 0; e < TE; e++) {
        int eg = e0 + e;
        if (eg < E) {
            int r = ei[eg];
            int c = ei[E + eg];
            s_ein[e][j]     = h[r * H + j];
            s_ein[e][H + j] = h[c * H + j];
            if (j == 0) {
                float rx = x[r * 3 + 0] - x[c * 3 + 0];
                float ry = x[r * 3 + 1] - x[c * 3 + 1];
                float rz = x[r * 3 + 2] - x[c * 3 + 2];
                s_rel[e][0] = rx; s_rel[e][1] = ry; s_rel[e][2] = rz;
                s_ein[e][2 * H] = rx * rx + ry * ry + rz * rz;
                s_row[e] = r;
            }
        } else {
            s_ein[e][j] = 0.0f; s_ein[e][H + j] = 0.0f;
            if (j == 0) {
                s_ein[e][2 * H] = 0.0f; s_row[e] = -1;
                s_rel[e][0] = s_rel[e][1] = s_rel[e][2] = 0.0f;
            }
        }
    }
    __syncthreads();

    // ---- Layer e1: 257 -> 128 ----
    {
        float acc[TE];
        float b = be1[j];
        #pragma unroll
        for (int e = 0; e < TE; e++) acc[e] = b;
        for (int kk = 0; kk < 64; kk++) {
            int k = kk * 4;
            float w0 = We1[(k + 0) * H + j];
            float w1 = We1[(k + 1) * H + j];
            float w2 = We1[(k + 2) * H + j];
            float w3 = We1[(k + 3) * H + j];
            #pragma unroll
            for (int e = 0; e < TE; e++) {
                float4 a = *(const float4*)&s_ein[e][k];
                acc[e] += a.x * w0 + a.y * w1 + a.z * w2 + a.w * w3;
            }
        }
        float wl = We1[256 * H + j];
        #pragma unroll
        for (int e = 0; e < TE; e++) acc[e] += s_ein[e][256] * wl;
        #pragma unroll
        for (int e = 0; e < TE; e++) s_f1[e][j] = silu(acc[e]);
    }
    __syncthreads();

    // ---- Layer e2: 128 -> 128 ----
    {
        float acc[TE];
        float b = be2[j];
        #pragma unroll
        for (int e = 0; e < TE; e++) acc[e] = b;
        for (int kk = 0; kk < 32; kk++) {
            int k = kk * 4;
            float w0 = We2[(k + 0) * H + j];
            float w1 = We2[(k + 1) * H + j];
            float w2 = We2[(k + 2) * H + j];
            float w3 = We2[(k + 3) * H + j];
            #pragma unroll
            for (int e = 0; e < TE; e++) {
                float4 a = *(const float4*)&s_f1[e][k];
                acc[e] += a.x * w0 + a.y * w1 + a.z * w2 + a.w * w3;
            }
        }
        #pragma unroll
        for (int e = 0; e < TE; e++) s_f2[e][j] = silu(acc[e]);
    }
    __syncthreads();

    // ---- Gate hidden: 128 -> 128 ----
    {
        float acc[TE];
        float b = bc1[j];
        #pragma unroll
        for (int e = 0; e < TE; e++) acc[e] = b;
        for (int kk = 0; kk < 32; kk++) {
            int k = kk * 4;
            float w0 = Wc1[(k + 0) * H + j];
            float w1 = Wc1[(k + 1) * H + j];
            float w2 = Wc1[(k + 2) * H + j];
            float w3 = Wc1[(k + 3) * H + j];
            #pragma unroll
            for (int e = 0; e < TE; e++) {
                float4 a = *(const float4*)&s_f2[e][k];
                acc[e] += a.x * w0 + a.y * w1 + a.z * w2 + a.w * w3;
            }
        }
        #pragma unroll
        for (int e = 0; e < TE; e++) s_g[e][j] = silu(acc[e]);
    }
    __syncthreads();

    // ---- Gate reduce: 128 -> 1 per edge ----
    {
        float bc2v = bc2[0];
        int wid = j >> 5, lane = j & 31;
        for (int e = wid; e < TE; e += 4) {
            float p = s_g[e][lane]      * s_wc2[lane]
                    + s_g[e][lane + 32] * s_wc2[lane + 32]
                    + s_g[e][lane + 64] * s_wc2[lane + 64]
                    + s_g[e][lane + 96] * s_wc2[lane + 96];
            #pragma unroll
            for (int off = 16; off > 0; off >>= 1)
                p += __shfl_down_sync(0xffffffffu, p, off);
            if (lane == 0) s_gate[e] = p + bc2v;
        }
    }
    __syncthreads();

    // ---- Scatter ----
    #pragma unroll
    for (int e = 0; e < TE; e++) {
        int r = s_row[e];
        if (r >= 0) {
            atomicAdd(&g_agg[r * H + j], s_f2[e][j]);
            if (j < 3) {
                atomicAdd(&g_dx[r * 3 + j], s_rel[e][j] * s_gate[e]);
            }
            if (j == 3) {
                atomicAdd(&g_cnt[r], 1.0f);
            }
        }
    }
}

// ---------------------------------------------------------------------------
// Node kernel: nin = [h, agg/cnt] (256)
//   n1 = silu(nin @ Wn1 + bn1); dh = n1 @ Wn2 + bn2; h2 = h + dh
//   h_out = silu(LayerNorm(h2) * gamma + beta)
//   x_out = x + dx/cnt
// ---------------------------------------------------------------------------
__global__ __launch_bounds__(128) void node_kernel(
    const float* __restrict__ x, const float* __restrict__ h, int n,
    const float* __restrict__ Wn1, const float* __restrict__ bn1,
    const float* __restrict__ Wn2, const float* __restrict__ bn2,
    const float* __restrict__ gamma, const float* __restrict__ beta,
    float* __restrict__ xout, float* __restrict__ hout)
{
    __shared__ float s_in[TN][2 * H];
    __shared__ float s_h1[TN][H];
    __shared__ float s_h2[TN][H];
    __shared__ float s_mu[TN], s_rs[TN];

    const int j = threadIdx.x;
    const int n0 = blockIdx.x * TN;

    #pragma unroll
    for (int e = 0; e < TN; e++) {
        int ng = n0 + e;
        if (ng < n) {
            float c = g_cnt[ng];
            c = c < 1.0f ? 1.0f : c;
            s_in[e][j]     = h[ng * H + j];
            s_in[e][H + j] = g_agg[ng * H + j] / c;
        } else {
            s_in[e][j] = 0.0f; s_in[e][H + j] = 0.0f;
        }
    }
    __syncthreads();

    // ---- Layer n1: 256 -> 128 ----
    {
        float acc[TN];
        float b = bn1[j];
        #pragma unroll
        for (int e = 0; e < TN; e++) acc[e] = b;
        for (int kk = 0; kk < 64; kk++) {
            int k = kk * 4;
            float w0 = Wn1[(k + 0) * H + j];
            float w1 = Wn1[(k + 1) * H + j];
            float w2 = Wn1[(k + 2) * H + j];
            float w3 = Wn1[(k + 3) * H + j];
            #pragma unroll
            for (int e = 0; e < TN; e++) {
                float4 a = *(const float4*)&s_in[e][k];
                acc[e] += a.x * w0 + a.y * w1 + a.z * w2 + a.w * w3;
            }
        }
        #pragma unroll
        for (int e = 0; e < TN; e++) s_h1[e][j] = silu(acc[e]);
    }
    __syncthreads();

    // ---- Layer n2: 128 -> 128, residual ----
    {
        float acc[TN];
        float b = bn2[j];
        #pragma unroll
        for (int e = 0; e < TN; e++) acc[e] = b;
        for (int kk = 0; kk < 32; kk++) {
            int k = kk * 4;
            float w0 = Wn2[(k + 0) * H + j];
            float w1 = Wn2[(k + 1) * H + j];
            float w2 = Wn2[(k + 2) * H + j];
            float w3 = Wn2[(k + 3) * H + j];
            #pragma unroll
            for (int e = 0; e < TN; e++) {
                float4 a = *(const float4*)&s_h1[e][k];
                acc[e] += a.x * w0 + a.y * w1 + a.z * w2 + a.w * w3;
            }
        }
        #pragma unroll
        for (int e = 0; e < TN; e++) {
            int ng = n0 + e;
            float hv = (ng < n) ? h[ng * H + j] : 0.0f;
            s_h2[e][j] = hv + acc[e];
        }
    }
    __syncthreads();

    // ---- LayerNorm stats: one warp handles 2 nodes ----
    {
        int wid = j >> 5, lane = j & 31;
        #pragma unroll
        for (int q = 0; q < 2; q++) {
            int e = wid * 2 + q;
            float v0 = s_h2[e][lane];
            float v1 = s_h2[e][lane + 32];
            float v2 = s_h2[e][lane + 64];
            float v3 = s_h2[e][lane + 96];
            float s = v0 + v1 + v2 + v3;
            float ss = v0 * v0 + v1 * v1 + v2 * v2 + v3 * v3;
            #pragma unroll
            for (int off = 16; off > 0; off >>= 1) {
                s  += __shfl_down_sync(0xffffffffu, s, off);
                ss += __shfl_down_sync(0xffffffffu, ss, off);
            }
            if (lane == 0) {
                float mu = s * (1.0f / H);
                float var = ss * (1.0f / H) - mu * mu;
                s_mu[e] = mu;
                s_rs[e] = rsqrtf(var + 1e-5f);
            }
        }
    }
    __syncthreads();

    // ---- Normalize + SiLU + outputs ----
    float gj = gamma[j], bj = beta[j];
    #pragma unroll
    for (int e = 0; e < TN; e++) {
        int ng = n0 + e;
        if (ng < n) {
            float v = (s_h2[e][j] - s_mu[e]) * s_rs[e] * gj + bj;
            hout[ng * H + j] = silu(v);
            if (j < 3) {
                float c = g_cnt[ng];
                c = c < 1.0f ? 1.0f : c;
                xout[ng * 3 + j] = x[ng * 3 + j] + g_dx[ng * 3 + j] / c;
            }
        }
    }
}

extern "C" void kernel_launch(void* const* d_in, const int* in_sizes, int n_in,
                              void* d_out, int out_size)
{
    const float* x    = (const float*)d_in[0];
    const float* h    = (const float*)d_in[1];
    const int*   ei   = (const int*)d_in[2];
    const float* We1  = (const float*)d_in[3];
    const float* be1  = (const float*)d_in[4];
    const float* We2  = (const float*)d_in[5];
    const float* be2  = (const float*)d_in[6];
    const float* Wc1  = (const float*)d_in[7];
    const float* bc1  = (const float*)d_in[8];
    const float* Wc2  = (const float*)d_in[9];
    const float* bc2  = (const float*)d_in[10];
    const float* Wn1  = (const float*)d_in[11];
    const float* bn1  = (const float*)d_in[12];
    const float* Wn2  = (const float*)d_in[13];
    const float* bn2  = (const float*)d_in[14];
    const float* gamma = (const float*)d_in[15];
    const float* beta  = (const float*)d_in[16];

    int n = in_sizes[0] / 3;       // 50000
    int E = in_sizes[2] / 2;       // 800000

    float* xout = (float*)d_out;              // [n,3]
    float* hout = xout + (size_t)n * 3;       // [n,128]

    zero_kernel<<<256, 256>>>(n);
    edge_kernel<<<(E + TE - 1) / TE, 128>>>(x, h, ei, E, n,
                                            We1, be1, We2, be2,
                                            Wc1, bc1, Wc2, bc2);
    node_kernel<<<(n + TN - 1) / TN, 128>>>(x, h, n, Wn1, bn1, Wn2, bn2,
                                            gamma, beta, xout, hout);
}

// round 2
// speedup vs baseline: 1.2462x; 1.2462x over previous
#include <cuda_runtime.h>

#define H 128
#define NMAX 50000
#define TP 8          // edge pairs per block (16 edges)
#define TE (2*TP)
#define TNP 4         // node pairs per block (8 nodes)
#define TN (2*TNP)

// Scratch accumulators (no dynamic allocation allowed)
__device__ float g_agg[NMAX * H];
__device__ float g_dx[NMAX * 3];
__device__ float g_cnt[NMAX];

typedef unsigned long long u64;

__device__ __forceinline__ void ffma2(u64 &acc, u64 a, u64 b) {
    asm("fma.rn.f32x2 %0, %1, %2, %0;" : "+l"(acc) : "l"(a), "l"(b));
}
__device__ __forceinline__ u64 pack2(float v) {
    u64 r; unsigned u = __float_as_uint(v);
    asm("mov.b64 %0, {%1, %1};" : "=l"(r) : "r"(u));
    return r;
}
__device__ __forceinline__ float2 unpack2(u64 v) {
    unsigned lo, hi;
    asm("mov.b64 {%0, %1}, %2;" : "=r"(lo), "=r"(hi) : "l"(v));
    return make_float2(__uint_as_float(lo), __uint_as_float(hi));
}
__device__ __forceinline__ float silu(float v) {
    return v / (1.0f + __expf(-v));
}

__global__ void zero_kernel(int n) {
    int total = n * H + n * 3 + n;
    for (int i = blockIdx.x * blockDim.x + threadIdx.x; i < total;
         i += gridDim.x * blockDim.x) {
        if (i < n * H) g_agg[i] = 0.0f;
        else if (i < n * H + n * 3) g_dx[i - n * H] = 0.0f;
        else g_cnt[i - n * H - n * 3] = 0.0f;
    }
}

// ---------------------------------------------------------------------------
// Edge kernel, f32x2-packed: 2 edges per 64-bit accumulator lane-half.
// 128 threads: thread j owns output column j; 8 edge-pairs in packed accums.
// ---------------------------------------------------------------------------
__global__ __launch_bounds__(128) void edge_kernel(
    const float* __restrict__ x, const float* __restrict__ h,
    const int* __restrict__ ei, int E, int n,
    const float* __restrict__ We1, const float* __restrict__ be1,
    const float* __restrict__ We2, const float* __restrict__ be2,
    const float* __restrict__ Wc1, const float* __restrict__ bc1,
    const float* __restrict__ Wc2, const float* __restrict__ bc2)
{
    __shared__ float2 s_ein[TP][258];   // cols 0..256 pair-interleaved, pad 258
    __shared__ float2 s_f1[TP][H];
    __shared__ float2 s_f2[TP][H];
    __shared__ float2 s_g[TP][H];
    __shared__ float  s_rel[TE][3];
    __shared__ int    s_row[TE];
    __shared__ float  s_gate[TE];
    __shared__ float  s_wc2[H];

    const int j = threadIdx.x;
    const long e0 = (long)blockIdx.x * TE;

    s_wc2[j] = Wc2[j];

    // Stage edge inputs, pair-interleaved
    #pragma unroll
    for (int p = 0; p < TP; p++) {
        long ea = e0 + 2 * p, eb = ea + 1;
        int ra = (ea < E) ? ei[ea] : -1;
        int rb = (eb < E) ? ei[eb] : -1;
        int ca = (ea < E) ? ei[E + ea] : 0;
        int cb = (eb < E) ? ei[E + eb] : 0;
        float h_ra = (ra >= 0) ? h[(long)ra * H + j] : 0.0f;
        float h_rb = (rb >= 0) ? h[(long)rb * H + j] : 0.0f;
        float h_ca = (ra >= 0) ? h[(long)ca * H + j] : 0.0f;
        float h_cb = (rb >= 0) ? h[(long)cb * H + j] : 0.0f;
        s_ein[p][j]     = make_float2(h_ra, h_rb);
        s_ein[p][H + j] = make_float2(h_ca, h_cb);
        if (j < 2) {
            int e = 2 * p + j;
            int r = (j == 0) ? ra : rb;
            int c = (j == 0) ? ca : cb;
            float rx = 0.f, ry = 0.f, rz = 0.f, d2 = 0.f;
            if (r >= 0) {
                rx = x[r * 3 + 0] - x[c * 3 + 0];
                ry = x[r * 3 + 1] - x[c * 3 + 1];
                rz = x[r * 3 + 2] - x[c * 3 + 2];
                d2 = rx * rx + ry * ry + rz * rz;
            }
            s_rel[e][0] = rx; s_rel[e][1] = ry; s_rel[e][2] = rz;
            s_row[e] = r;
            ((float*)&s_ein[p][256])[j] = d2;
        }
    }
    __syncthreads();

    u64 acc[TP];

    // ---- Layer e1: 257 -> 128 ----
    {
        u64 b2 = pack2(be1[j]);
        #pragma unroll
        for (int p = 0; p < TP; p++) acc[p] = b2;
        #pragma unroll 4
        for (int kk = 0; kk < 64; kk++) {
            int k = kk * 4;
            u64 w0 = pack2(We1[(k + 0) * H + j]);
            u64 w1 = pack2(We1[(k + 1) * H + j]);
            u64 w2 = pack2(We1[(k + 2) * H + j]);
            u64 w3 = pack2(We1[(k + 3) * H + j]);
            #pragma unroll
            for (int p = 0; p < TP; p++) {
                ulonglong2 A0 = *(const ulonglong2*)&s_ein[p][k];
                ulonglong2 A1 = *(const ulonglong2*)&s_ein[p][k + 2];
                ffma2(acc[p], A0.x, w0);
                ffma2(acc[p], A0.y, w1);
                ffma2(acc[p], A1.x, w2);
                ffma2(acc[p], A1.y, w3);
            }
        }
        u64 wl = pack2(We1[256 * H + j]);
        #pragma unroll
        for (int p = 0; p < TP; p++) {
            u64 a = *(const u64*)&s_ein[p][256];
            ffma2(acc[p], a, wl);
            float2 v = unpack2(acc[p]);
            s_f1[p][j] = make_float2(silu(v.x), silu(v.y));
        }
    }
    __syncthreads();

    // ---- Layer e2: 128 -> 128 ----
    {
        u64 b2 = pack2(be2[j]);
        #pragma unroll
        for (int p = 0; p < TP; p++) acc[p] = b2;
        #pragma unroll 4
        for (int kk = 0; kk < 32; kk++) {
            int k = kk * 4;
            u64 w0 = pack2(We2[(k + 0) * H + j]);
            u64 w1 = pack2(We2[(k + 1) * H + j]);
            u64 w2 = pack2(We2[(k + 2) * H + j]);
            u64 w3 = pack2(We2[(k + 3) * H + j]);
            #pragma unroll
            for (int p = 0; p < TP; p++) {
                ulonglong2 A0 = *(const ulonglong2*)&s_f1[p][k];
                ulonglong2 A1 = *(const ulonglong2*)&s_f1[p][k + 2];
                ffma2(acc[p], A0.x, w0);
                ffma2(acc[p], A0.y, w1);
                ffma2(acc[p], A1.x, w2);
                ffma2(acc[p], A1.y, w3);
            }
        }
        #pragma unroll
        for (int p = 0; p < TP; p++) {
            float2 v = unpack2(acc[p]);
            s_f2[p][j] = make_float2(silu(v.x), silu(v.y));
        }
    }
    __syncthreads();

    // ---- Gate hidden: 128 -> 128 ----
    {
        u64 b2 = pack2(bc1[j]);
        #pragma unroll
        for (int p = 0; p < TP; p++) acc[p] = b2;
        #pragma unroll 4
        for (int kk = 0; kk < 32; kk++) {
            int k = kk * 4;
            u64 w0 = pack2(Wc1[(k + 0) * H + j]);
            u64 w1 = pack2(Wc1[(k + 1) * H + j]);
            u64 w2 = pack2(Wc1[(k + 2) * H + j]);
            u64 w3 = pack2(Wc1[(k + 3) * H + j]);
            #pragma unroll
            for (int p = 0; p < TP; p++) {
                ulonglong2 A0 = *(const ulonglong2*)&s_f2[p][k];
                ulonglong2 A1 = *(const ulonglong2*)&s_f2[p][k + 2];
                ffma2(acc[p], A0.x, w0);
                ffma2(acc[p], A0.y, w1);
                ffma2(acc[p], A1.x, w2);
                ffma2(acc[p], A1.y, w3);
            }
        }
        #pragma unroll
        for (int p = 0; p < TP; p++) {
            float2 v = unpack2(acc[p]);
            s_g[p][j] = make_float2(silu(v.x), silu(v.y));
        }
    }
    __syncthreads();

    // ---- Gate reduce: 128 -> 1 per edge ----
    {
        float bc2v = bc2[0];
        int wid = j >> 5, lane = j & 31;
        for (int e = wid; e < TE; e += 4) {
            int p = e >> 1, hf = e & 1;
            const float* gp = (const float*)&s_g[p][0];  // col c at gp[2c+hf]
            float ps = gp[2 * lane + hf]        * s_wc2[lane]
                     + gp[2 * (lane + 32) + hf] * s_wc2[lane + 32]
                     + gp[2 * (lane + 64) + hf] * s_wc2[lane + 64]
                     + gp[2 * (lane + 96) + hf] * s_wc2[lane + 96];
            #pragma unroll
            for (int off = 16; off > 0; off >>= 1)
                ps += __shfl_down_sync(0xffffffffu, ps, off);
            if (lane == 0) s_gate[e] = ps + bc2v;
        }
    }
    __syncthreads();

    // ---- Scatter ----
    #pragma unroll
    for (int p = 0; p < TP; p++) {
        float2 f = s_f2[p][j];
        int r0 = s_row[2 * p], r1 = s_row[2 * p + 1];
        if (r0 >= 0) atomicAdd(&g_agg[(long)r0 * H + j], f.x);
        if (r1 >= 0) atomicAdd(&g_agg[(long)r1 * H + j], f.y);
    }
    if (j < TE * 4) {
        int e = j >> 2, c = j & 3;
        int r = s_row[e];
        if (r >= 0) {
            if (c < 3) atomicAdd(&g_dx[r * 3 + c], s_rel[e][c] * s_gate[e]);
            else       atomicAdd(&g_cnt[r], 1.0f);
        }
    }
}

// ---------------------------------------------------------------------------
// Node kernel, f32x2-packed GEMMs; scalar LayerNorm epilogue.
// ---------------------------------------------------------------------------
__global__ __launch_bounds__(128) void node_kernel(
    const float* __restrict__ x, const float* __restrict__ h, int n,
    const float* __restrict__ Wn1, const float* __restrict__ bn1,
    const float* __restrict__ Wn2, const float* __restrict__ bn2,
    const float* __restrict__ gamma, const float* __restrict__ beta,
    float* __restrict__ xout, float* __restrict__ hout)
{
    __shared__ float2 s_in[TNP][2 * H];
    __shared__ float2 s_h1[TNP][H];
    __shared__ float  s_h2[TN][H];
    __shared__ float  s_mu[TN], s_rs[TN];

    const int j = threadIdx.x;
    const int n0 = blockIdx.x * TN;

    #pragma unroll
    for (int p = 0; p < TNP; p++) {
        int na = n0 + 2 * p, nb = na + 1;
        float ha = 0.f, hb = 0.f, aa = 0.f, ab = 0.f;
        if (na < n) {
            float c = g_cnt[na]; c = c < 1.0f ? 1.0f : c;
            ha = h[(long)na * H + j];
            aa = g_agg[(long)na * H + j] / c;
        }
        if (nb < n) {
            float c = g_cnt[nb]; c = c < 1.0f ? 1.0f : c;
            hb = h[(long)nb * H + j];
            ab = g_agg[(long)nb * H + j] / c;
        }
        s_in[p][j]     = make_float2(ha, hb);
        s_in[p][H + j] = make_float2(aa, ab);
    }
    __syncthreads();

    u64 acc[TNP];

    // ---- Layer n1: 256 -> 128 ----
    {
        u64 b2 = pack2(bn1[j]);
        #pragma unroll
        for (int p = 0; p < TNP; p++) acc[p] = b2;
        #pragma unroll 4
        for (int kk = 0; kk < 64; kk++) {
            int k = kk * 4;
            u64 w0 = pack2(Wn1[(k + 0) * H + j]);
            u64 w1 = pack2(Wn1[(k + 1) * H + j]);
            u64 w2 = pack2(Wn1[(k + 2) * H + j]);
            u64 w3 = pack2(Wn1[(k + 3) * H + j]);
            #pragma unroll
            for (int p = 0; p < TNP; p++) {
                ulonglong2 A0 = *(const ulonglong2*)&s_in[p][k];
                ulonglong2 A1 = *(const ulonglong2*)&s_in[p][k + 2];
                ffma2(acc[p], A0.x, w0);
                ffma2(acc[p], A0.y, w1);
                ffma2(acc[p], A1.x, w2);
                ffma2(acc[p], A1.y, w3);
            }
        }
        #pragma unroll
        for (int p = 0; p < TNP; p++) {
            float2 v = unpack2(acc[p]);
            s_h1[p][j] = make_float2(silu(v.x), silu(v.y));
        }
    }
    __syncthreads();

    // ---- Layer n2: 128 -> 128, residual ----
    {
        u64 b2 = pack2(bn2[j]);
        #pragma unroll
        for (int p = 0; p < TNP; p++) acc[p] = b2;
        #pragma unroll 4
        for (int kk = 0; kk < 32; kk++) {
            int k = kk * 4;
            u64 w0 = pack2(Wn2[(k + 0) * H + j]);
            u64 w1 = pack2(Wn2[(k + 1) * H + j]);
            u64 w2 = pack2(Wn2[(k + 2) * H + j]);
            u64 w3 = pack2(Wn2[(k + 3) * H + j]);
            #pragma unroll
            for (int p = 0; p < TNP; p++) {
                ulonglong2 A0 = *(const ulonglong2*)&s_h1[p][k];
                ulonglong2 A1 = *(const ulonglong2*)&s_h1[p][k + 2];
                ffma2(acc[p], A0.x, w0);
                ffma2(acc[p], A0.y, w1);
                ffma2(acc[p], A1.x, w2);
                ffma2(acc[p], A1.y, w3);
            }
        }
        #pragma unroll
        for (int p = 0; p < TNP; p++) {
            int na = n0 + 2 * p, nb = na + 1;
            float2 v = unpack2(acc[p]);
            float ha = (na < n) ? h[(long)na * H + j] : 0.0f;
            float hb = (nb < n) ? h[(long)nb * H + j] : 0.0f;
            s_h2[2 * p][j]     = ha + v.x;
            s_h2[2 * p + 1][j] = hb + v.y;
        }
    }
    __syncthreads();

    // ---- LayerNorm stats: one warp per 2 nodes ----
    {
        int wid = j >> 5, lane = j & 31;
        #pragma unroll
        for (int q = 0; q < 2; q++) {
            int e = wid * 2 + q;
            float v0 = s_h2[e][lane];
            float v1 = s_h2[e][lane + 32];
            float v2 = s_h2[e][lane + 64];
            float v3 = s_h2[e][lane + 96];
            float s  = v0 + v1 + v2 + v3;
            float ss = v0 * v0 + v1 * v1 + v2 * v2 + v3 * v3;
            #pragma unroll
            for (int off = 16; off > 0; off >>= 1) {
                s  += __shfl_down_sync(0xffffffffu, s, off);
                ss += __shfl_down_sync(0xffffffffu, ss, off);
            }
            if (lane == 0) {
                float mu = s * (1.0f / H);
                float var = ss * (1.0f / H) - mu * mu;
                s_mu[e] = mu;
                s_rs[e] = rsqrtf(var + 1e-5f);
            }
        }
    }
    __syncthreads();

    // ---- Normalize + SiLU + outputs ----
    float gj = gamma[j], bj = beta[j];
    #pragma unroll
    for (int e = 0; e < TN; e++) {
        int ng = n0 + e;
        if (ng < n) {
            float v = (s_h2[e][j] - s_mu[e]) * s_rs[e] * gj + bj;
            hout[(long)ng * H + j] = silu(v);
            if (j < 3) {
                float c = g_cnt[ng]; c = c < 1.0f ? 1.0f : c;
                xout[ng * 3 + j] = x[ng * 3 + j] + g_dx[ng * 3 + j] / c;
            }
        }
    }
}

extern "C" void kernel_launch(void* const* d_in, const int* in_sizes, int n_in,
                              void* d_out, int out_size)
{
    const float* x    = (const float*)d_in[0];
    const float* h    = (const float*)d_in[1];
    const int*   ei   = (const int*)d_in[2];
    const float* We1  = (const float*)d_in[3];
    const float* be1  = (const float*)d_in[4];
    const float* We2  = (const float*)d_in[5];
    const float* be2  = (const float*)d_in[6];
    const float* Wc1  = (const float*)d_in[7];
    const float* bc1  = (const float*)d_in[8];
    const float* Wc2  = (const float*)d_in[9];
    const float* bc2  = (const float*)d_in[10];
    const float* Wn1  = (const float*)d_in[11];
    const float* bn1  = (const float*)d_in[12];
    const float* Wn2  = (const float*)d_in[13];
    const float* bn2  = (const float*)d_in[14];
    const float* gamma = (const float*)d_in[15];
    const float* beta  = (const float*)d_in[16];

    int n = in_sizes[0] / 3;       // 50000
    int E = in_sizes[2] / 2;       // 800000

    float* xout = (float*)d_out;              // [n,3]
    float* hout = xout + (size_t)n * 3;       // [n,128]

    zero_kernel<<<256, 256>>>(n);
    edge_kernel<<<(E + TE - 1) / TE, 128>>>(x, h, ei, E, n,
                                            We1, be1, We2, be2,
                                            Wc1, bc1, Wc2, bc2);
    node_kernel<<<(n + TN - 1) / TN, 128>>>(x, h, n, Wn1, bn1, Wn2, bn2,
                                            gamma, beta, xout, hout);
}

// round 3
// speedup vs baseline: 1.3286x; 1.0661x over previous
#include <cuda_runtime.h>

#define H 128
#define NMAX 50000
#define TP 8            // edge pairs per GROUP (16 edges/group)
#define GE (2*TP)       // edges per group
#define TE (2*GE)       // 32 edges per block (2 groups)
#define TNP 4           // node pairs per group
#define GN (2*TNP)      // 8 nodes per group
#define TN (2*GN)       // 16 nodes per block

// Scratch accumulators (no dynamic allocation allowed)
__device__ float g_agg[NMAX * H];
__device__ float g_dx[NMAX * 3];
__device__ float g_cnt[NMAX];

typedef unsigned long long u64;

__device__ __forceinline__ void ffma2(u64 &acc, u64 a, u64 b) {
    asm("fma.rn.f32x2 %0, %1, %2, %0;" : "+l"(acc) : "l"(a), "l"(b));
}
__device__ __forceinline__ u64 pack2(float v) {
    u64 r; unsigned u = __float_as_uint(v);
    asm("mov.b64 %0, {%1, %1};" : "=l"(r) : "r"(u));
    return r;
}
__device__ __forceinline__ float2 unpack2(u64 v) {
    unsigned lo, hi;
    asm("mov.b64 {%0, %1}, %2;" : "=r"(lo), "=r"(hi) : "l"(v));
    return make_float2(__uint_as_float(lo), __uint_as_float(hi));
}
__device__ __forceinline__ float silu(float v) {
    return v / (1.0f + __expf(-v));
}
__device__ __forceinline__ float2 silu2(u64 v) {
    float2 f = unpack2(v);
    return make_float2(silu(f.x), silu(f.y));
}

__global__ void zero_kernel(int n) {
    int total = n * H + n * 3 + n;
    for (int i = blockIdx.x * blockDim.x + threadIdx.x; i < total;
         i += gridDim.x * blockDim.x) {
        if (i < n * H) g_agg[i] = 0.0f;
        else if (i < n * H + n * 3) g_dx[i - n * H] = 0.0f;
        else g_cnt[i - n * H - n * 3] = 0.0f;
    }
}

// ---------------------------------------------------------------------------
// Edge kernel: 2 groups x 64 threads; thread owns output cols t and t+64.
// Each group: TP=8 edge-pairs in packed f32x2 accumulators.
// One LDS.128 feeds 4 FFMA2 (2 k x 2 cols) -> FMA-pipe bound.
// ---------------------------------------------------------------------------
__global__ __launch_bounds__(128) void edge_kernel(
    const float* __restrict__ x, const float* __restrict__ h,
    const int* __restrict__ ei, int E, int n,
    const float* __restrict__ We1, const float* __restrict__ be1,
    const float* __restrict__ We2, const float* __restrict__ be2,
    const float* __restrict__ Wc1, const float* __restrict__ bc1,
    const float* __restrict__ Wc2, const float* __restrict__ bc2)
{
    __shared__ float2 s_ein[2][TP][260];   // cols 0..256 pair-interleaved
    __shared__ float2 s_f1[2][TP][H];
    __shared__ float2 s_f2[2][TP][H];
    __shared__ float2 s_g[2][TP][H];
    __shared__ float  s_rel[TE][3];
    __shared__ int    s_row[TE];
    __shared__ float  s_gate[TE];
    __shared__ float  s_wc2[H];

    const int j = threadIdx.x;
    const int g = j >> 6;          // group 0/1
    const int t = j & 63;          // owns cols t, t+64
    const int c0 = t, c1 = t + 64;
    const long e0 = (long)blockIdx.x * TE + (long)g * GE;

    if (g == 0) s_wc2[t] = Wc2[t], s_wc2[t + 64] = Wc2[t + 64];

    // Stage edge inputs, pair-interleaved
    #pragma unroll
    for (int p = 0; p < TP; p++) {
        long ea = e0 + 2 * p, eb = ea + 1;
        int ra = (ea < E) ? ei[ea] : -1;
        int rb = (eb < E) ? ei[eb] : -1;
        int ca = (ea < E) ? ei[E + ea] : 0;
        int cb = (eb < E) ? ei[E + eb] : 0;
        const float* hra = (ra >= 0) ? h + (long)ra * H : 0;
        const float* hrb = (rb >= 0) ? h + (long)rb * H : 0;
        const float* hca = (ra >= 0) ? h + (long)ca * H : 0;
        const float* hcb = (rb >= 0) ? h + (long)cb * H : 0;
        float a0 = hra ? hra[c0] : 0.f, a1 = hra ? hra[c1] : 0.f;
        float b0 = hrb ? hrb[c0] : 0.f, b1 = hrb ? hrb[c1] : 0.f;
        s_ein[g][p][c0]       = make_float2(a0, b0);
        s_ein[g][p][c1]       = make_float2(a1, b1);
        a0 = hca ? hca[c0] : 0.f; a1 = hca ? hca[c1] : 0.f;
        b0 = hcb ? hcb[c0] : 0.f; b1 = hcb ? hcb[c1] : 0.f;
        s_ein[g][p][H + c0]   = make_float2(a0, b0);
        s_ein[g][p][H + c1]   = make_float2(a1, b1);
        if (t < 2) {
            int e = g * GE + 2 * p + t;
            int r = (t == 0) ? ra : rb;
            int c = (t == 0) ? ca : cb;
            float rx = 0.f, ry = 0.f, rz = 0.f, d2 = 0.f;
            if (r >= 0) {
                rx = x[r * 3 + 0] - x[c * 3 + 0];
                ry = x[r * 3 + 1] - x[c * 3 + 1];
                rz = x[r * 3 + 2] - x[c * 3 + 2];
                d2 = rx * rx + ry * ry + rz * rz;
            }
            s_rel[e][0] = rx; s_rel[e][1] = ry; s_rel[e][2] = rz;
            s_row[e] = r;
            ((float*)&s_ein[g][p][256])[t] = d2;
        }
    }
    __syncthreads();

    u64 acc0[TP], acc1[TP];

    // ---- Layer e1: 257 -> 128 ----
    {
        u64 ba = pack2(be1[c0]), bb = pack2(be1[c1]);
        #pragma unroll
        for (int p = 0; p < TP; p++) { acc0[p] = ba; acc1[p] = bb; }
        #pragma unroll 2
        for (int kk = 0; kk < 64; kk++) {
            int k = kk * 4;
            u64 wa0 = pack2(We1[(k + 0) * H + c0]);
            u64 wa1 = pack2(We1[(k + 1) * H + c0]);
            u64 wa2 = pack2(We1[(k + 2) * H + c0]);
            u64 wa3 = pack2(We1[(k + 3) * H + c0]);
            u64 wb0 = pack2(We1[(k + 0) * H + c1]);
            u64 wb1 = pack2(We1[(k + 1) * H + c1]);
            u64 wb2 = pack2(We1[(k + 2) * H + c1]);
            u64 wb3 = pack2(We1[(k + 3) * H + c1]);
            #pragma unroll
            for (int p = 0; p < TP; p++) {
                ulonglong2 A0 = *(const ulonglong2*)&s_ein[g][p][k];
                ulonglong2 A1 = *(const ulonglong2*)&s_ein[g][p][k + 2];
                ffma2(acc0[p], A0.x, wa0); ffma2(acc1[p], A0.x, wb0);
                ffma2(acc0[p], A0.y, wa1); ffma2(acc1[p], A0.y, wb1);
                ffma2(acc0[p], A1.x, wa2); ffma2(acc1[p], A1.x, wb2);
                ffma2(acc0[p], A1.y, wa3); ffma2(acc1[p], A1.y, wb3);
            }
        }
        u64 wla = pack2(We1[256 * H + c0]), wlb = pack2(We1[256 * H + c1]);
        #pragma unroll
        for (int p = 0; p < TP; p++) {
            u64 a = *(const u64*)&s_ein[g][p][256];
            ffma2(acc0[p], a, wla);
            ffma2(acc1[p], a, wlb);
            s_f1[g][p][c0] = silu2(acc0[p]);
            s_f1[g][p][c1] = silu2(acc1[p]);
        }
    }
    __syncthreads();

    // ---- Layer e2: 128 -> 128 ----
    {
        u64 ba = pack2(be2[c0]), bb = pack2(be2[c1]);
        #pragma unroll
        for (int p = 0; p < TP; p++) { acc0[p] = ba; acc1[p] = bb; }
        #pragma unroll 2
        for (int kk = 0; kk < 32; kk++) {
            int k = kk * 4;
            u64 wa0 = pack2(We2[(k + 0) * H + c0]);
            u64 wa1 = pack2(We2[(k + 1) * H + c0]);
            u64 wa2 = pack2(We2[(k + 2) * H + c0]);
            u64 wa3 = pack2(We2[(k + 3) * H + c0]);
            u64 wb0 = pack2(We2[(k + 0) * H + c1]);
            u64 wb1 = pack2(We2[(k + 1) * H + c1]);
            u64 wb2 = pack2(We2[(k + 2) * H + c1]);
            u64 wb3 = pack2(We2[(k + 3) * H + c1]);
            #pragma unroll
            for (int p = 0; p < TP; p++) {
                ulonglong2 A0 = *(const ulonglong2*)&s_f1[g][p][k];
                ulonglong2 A1 = *(const ulonglong2*)&s_f1[g][p][k + 2];
                ffma2(acc0[p], A0.x, wa0); ffma2(acc1[p], A0.x, wb0);
                ffma2(acc0[p], A0.y, wa1); ffma2(acc1[p], A0.y, wb1);
                ffma2(acc0[p], A1.x, wa2); ffma2(acc1[p], A1.x, wb2);
                ffma2(acc0[p], A1.y, wa3); ffma2(acc1[p], A1.y, wb3);
            }
        }
        #pragma unroll
        for (int p = 0; p < TP; p++) {
            s_f2[g][p][c0] = silu2(acc0[p]);
            s_f2[g][p][c1] = silu2(acc1[p]);
        }
    }
    __syncthreads();

    // ---- Gate hidden: 128 -> 128 ----
    {
        u64 ba = pack2(bc1[c0]), bb = pack2(bc1[c1]);
        #pragma unroll
        for (int p = 0; p < TP; p++) { acc0[p] = ba; acc1[p] = bb; }
        #pragma unroll 2
        for (int kk = 0; kk < 32; kk++) {
            int k = kk * 4;
            u64 wa0 = pack2(Wc1[(k + 0) * H + c0]);
            u64 wa1 = pack2(Wc1[(k + 1) * H + c0]);
            u64 wa2 = pack2(Wc1[(k + 2) * H + c0]);
            u64 wa3 = pack2(Wc1[(k + 3) * H + c0]);
            u64 wb0 = pack2(Wc1[(k + 0) * H + c1]);
            u64 wb1 = pack2(Wc1[(k + 1) * H + c1]);
            u64 wb2 = pack2(Wc1[(k + 2) * H + c1]);
            u64 wb3 = pack2(Wc1[(k + 3) * H + c1]);
            #pragma unroll
            for (int p = 0; p < TP; p++) {
                ulonglong2 A0 = *(const ulonglong2*)&s_f2[g][p][k];
                ulonglong2 A1 = *(const ulonglong2*)&s_f2[g][p][k + 2];
                ffma2(acc0[p], A0.x, wa0); ffma2(acc1[p], A0.x, wb0);
                ffma2(acc0[p], A0.y, wa1); ffma2(acc1[p], A0.y, wb1);
                ffma2(acc0[p], A1.x, wa2); ffma2(acc1[p], A1.x, wb2);
                ffma2(acc0[p], A1.y, wa3); ffma2(acc1[p], A1.y, wb3);
            }
        }
        #pragma unroll
        for (int p = 0; p < TP; p++) {
            s_g[g][p][c0] = silu2(acc0[p]);
            s_g[g][p][c1] = silu2(acc1[p]);
        }
    }
    __syncthreads();

    // ---- Gate reduce: 128 -> 1 per edge (4 warps over 32 edges) ----
    {
        float bc2v = bc2[0];
        int wid = j >> 5, lane = j & 31;
        for (int e = wid; e < TE; e += 4) {
            int eg = e >> 4, pe = (e & 15) >> 1, hf = e & 1;
            const float* gp = (const float*)&s_g[eg][pe][0]; // col c at gp[2c+hf]
            float ps = gp[2 * lane + hf]        * s_wc2[lane]
                     + gp[2 * (lane + 32) + hf] * s_wc2[lane + 32]
                     + gp[2 * (lane + 64) + hf] * s_wc2[lane + 64]
                     + gp[2 * (lane + 96) + hf] * s_wc2[lane + 96];
            #pragma unroll
            for (int off = 16; off > 0; off >>= 1)
                ps += __shfl_down_sync(0xffffffffu, ps, off);
            if (lane == 0) s_gate[e] = ps + bc2v;
        }
    }
    __syncthreads();

    // ---- Scatter ----
    #pragma unroll
    for (int p = 0; p < TP; p++) {
        int r0 = s_row[g * GE + 2 * p], r1 = s_row[g * GE + 2 * p + 1];
        float2 fa = s_f2[g][p][c0];
        float2 fb = s_f2[g][p][c1];
        if (r0 >= 0) {
            atomicAdd(&g_agg[(long)r0 * H + c0], fa.x);
            atomicAdd(&g_agg[(long)r0 * H + c1], fb.x);
        }
        if (r1 >= 0) {
            atomicAdd(&g_agg[(long)r1 * H + c0], fa.y);
            atomicAdd(&g_agg[(long)r1 * H + c1], fb.y);
        }
    }
    {
        int e = j >> 2, c = j & 3;   // 128 threads cover 32 edges x 4
        int r = s_row[e];
        if (r >= 0) {
            if (c < 3) atomicAdd(&g_dx[r * 3 + c], s_rel[e][c] * s_gate[e]);
            else       atomicAdd(&g_cnt[r], 1.0f);
        }
    }
}

// ---------------------------------------------------------------------------
// Node kernel: same 2-group / 2-column structure.
// ---------------------------------------------------------------------------
__global__ __launch_bounds__(128) void node_kernel(
    const float* __restrict__ x, const float* __restrict__ h, int n,
    const float* __restrict__ Wn1, const float* __restrict__ bn1,
    const float* __restrict__ Wn2, const float* __restrict__ bn2,
    const float* __restrict__ gamma, const float* __restrict__ beta,
    float* __restrict__ xout, float* __restrict__ hout)
{
    __shared__ float2 s_in[2][TNP][2 * H];
    __shared__ float2 s_h1[2][TNP][H];
    __shared__ float  s_h2[TN][H];
    __shared__ float  s_mu[TN], s_rs[TN];

    const int j = threadIdx.x;
    const int g = j >> 6;
    const int t = j & 63;
    const int c0 = t, c1 = t + 64;
    const int n0 = blockIdx.x * TN + g * GN;

    #pragma unroll
    for (int p = 0; p < TNP; p++) {
        int na = n0 + 2 * p, nb = na + 1;
        float ha0 = 0.f, ha1 = 0.f, hb0 = 0.f, hb1 = 0.f;
        float aa0 = 0.f, aa1 = 0.f, ab0 = 0.f, ab1 = 0.f;
        if (na < n) {
            float c = g_cnt[na]; c = c < 1.0f ? 1.0f : c; float ic = 1.0f / c;
            ha0 = h[(long)na * H + c0]; ha1 = h[(long)na * H + c1];
            aa0 = g_agg[(long)na * H + c0] * ic; aa1 = g_agg[(long)na * H + c1] * ic;
        }
        if (nb < n) {
            float c = g_cnt[nb]; c = c < 1.0f ? 1.0f : c; float ic = 1.0f / c;
            hb0 = h[(long)nb * H + c0]; hb1 = h[(long)nb * H + c1];
            ab0 = g_agg[(long)nb * H + c0] * ic; ab1 = g_agg[(long)nb * H + c1] * ic;
        }
        s_in[g][p][c0]     = make_float2(ha0, hb0);
        s_in[g][p][c1]     = make_float2(ha1, hb1);
        s_in[g][p][H + c0] = make_float2(aa0, ab0);
        s_in[g][p][H + c1] = make_float2(aa1, ab1);
    }
    __syncthreads();

    u64 acc0[TNP], acc1[TNP];

    // ---- Layer n1: 256 -> 128 ----
    {
        u64 ba = pack2(bn1[c0]), bb = pack2(bn1[c1]);
        #pragma unroll
        for (int p = 0; p < TNP; p++) { acc0[p] = ba; acc1[p] = bb; }
        #pragma unroll 2
        for (int kk = 0; kk < 64; kk++) {
            int k = kk * 4;
            u64 wa0 = pack2(Wn1[(k + 0) * H + c0]);
            u64 wa1 = pack2(Wn1[(k + 1) * H + c0]);
            u64 wa2 = pack2(Wn1[(k + 2) * H + c0]);
            u64 wa3 = pack2(Wn1[(k + 3) * H + c0]);
            u64 wb0 = pack2(Wn1[(k + 0) * H + c1]);
            u64 wb1 = pack2(Wn1[(k + 1) * H + c1]);
            u64 wb2 = pack2(Wn1[(k + 2) * H + c1]);
            u64 wb3 = pack2(Wn1[(k + 3) * H + c1]);
            #pragma unroll
            for (int p = 0; p < TNP; p++) {
                ulonglong2 A0 = *(const ulonglong2*)&s_in[g][p][k];
                ulonglong2 A1 = *(const ulonglong2*)&s_in[g][p][k + 2];
                ffma2(acc0[p], A0.x, wa0); ffma2(acc1[p], A0.x, wb0);
                ffma2(acc0[p], A0.y, wa1); ffma2(acc1[p], A0.y, wb1);
                ffma2(acc0[p], A1.x, wa2); ffma2(acc1[p], A1.x, wb2);
                ffma2(acc0[p], A1.y, wa3); ffma2(acc1[p], A1.y, wb3);
            }
        }
        #pragma unroll
        for (int p = 0; p < TNP; p++) {
            s_h1[g][p][c0] = silu2(acc0[p]);
            s_h1[g][p][c1] = silu2(acc1[p]);
        }
    }
    __syncthreads();

    // ---- Layer n2: 128 -> 128, residual ----
    {
        u64 ba = pack2(bn2[c0]), bb = pack2(bn2[c1]);
        #pragma unroll
        for (int p = 0; p < TNP; p++) { acc0[p] = ba; acc1[p] = bb; }
        #pragma unroll 2
        for (int kk = 0; kk < 32; kk++) {
            int k = kk * 4;
            u64 wa0 = pack2(Wn2[(k + 0) * H + c0]);
            u64 wa1 = pack2(Wn2[(k + 1) * H + c0]);
            u64 wa2 = pack2(Wn2[(k + 2) * H + c0]);
            u64 wa3 = pack2(Wn2[(k + 3) * H + c0]);
            u64 wb0 = pack2(Wn2[(k + 0) * H + c1]);
            u64 wb1 = pack2(Wn2[(k + 1) * H + c1]);
            u64 wb2 = pack2(Wn2[(k + 2) * H + c1]);
            u64 wb3 = pack2(Wn2[(k + 3) * H + c1]);
            #pragma unroll
            for (int p = 0; p < TNP; p++) {
                ulonglong2 A0 = *(const ulonglong2*)&s_h1[g][p][k];
                ulonglong2 A1 = *(const ulonglong2*)&s_h1[g][p][k + 2];
                ffma2(acc0[p], A0.x, wa0); ffma2(acc1[p], A0.x, wb0);
                ffma2(acc0[p], A0.y, wa1); ffma2(acc1[p], A0.y, wb1);
                ffma2(acc0[p], A1.x, wa2); ffma2(acc1[p], A1.x, wb2);
                ffma2(acc0[p], A1.y, wa3); ffma2(acc1[p], A1.y, wb3);
            }
        }
        #pragma unroll
        for (int p = 0; p < TNP; p++) {
            int na = n0 + 2 * p, nb = na + 1;
            float2 va = unpack2(acc0[p]);
            float2 vb = unpack2(acc1[p]);
            float ha0 = (na < n) ? h[(long)na * H + c0] : 0.0f;
            float ha1 = (na < n) ? h[(long)na * H + c1] : 0.0f;
            float hb0 = (nb < n) ? h[(long)nb * H + c0] : 0.0f;
            float hb1 = (nb < n) ? h[(long)nb * H + c1] : 0.0f;
            int la = g * GN + 2 * p, lb = la + 1;
            s_h2[la][c0] = ha0 + va.x;
            s_h2[la][c1] = ha1 + vb.x;
            s_h2[lb][c0] = hb0 + va.y;
            s_h2[lb][c1] = hb1 + vb.y;
        }
    }
    __syncthreads();

    // ---- LayerNorm stats: 4 warps over 16 nodes ----
    {
        int wid = j >> 5, lane = j & 31;
        #pragma unroll
        for (int q = 0; q < 4; q++) {
            int e = wid * 4 + q;
            float v0 = s_h2[e][lane];
            float v1 = s_h2[e][lane + 32];
            float v2 = s_h2[e][lane + 64];
            float v3 = s_h2[e][lane + 96];
            float s  = v0 + v1 + v2 + v3;
            float ss = v0 * v0 + v1 * v1 + v2 * v2 + v3 * v3;
            #pragma unroll
            for (int off = 16; off > 0; off >>= 1) {
                s  += __shfl_down_sync(0xffffffffu, s, off);
                ss += __shfl_down_sync(0xffffffffu, ss, off);
            }
            if (lane == 0) {
                float mu = s * (1.0f / H);
                float var = ss * (1.0f / H) - mu * mu;
                s_mu[e] = mu;
                s_rs[e] = rsqrtf(var + 1e-5f);
            }
        }
    }
    __syncthreads();

    // ---- Normalize + SiLU + outputs ----
    const int nb0 = blockIdx.x * TN;
    float gj = gamma[j], bj = beta[j];
    #pragma unroll
    for (int e = 0; e < TN; e++) {
        int ng = nb0 + e;
        if (ng < n) {
            float v = (s_h2[e][j] - s_mu[e]) * s_rs[e] * gj + bj;
            hout[(long)ng * H + j] = silu(v);
            if (j < 3) {
                float c = g_cnt[ng]; c = c < 1.0f ? 1.0f : c;
                xout[ng * 3 + j] = x[ng * 3 + j] + g_dx[ng * 3 + j] / c;
            }
        }
    }
}

extern "C" void kernel_launch(void* const* d_in, const int* in_sizes, int n_in,
                              void* d_out, int out_size)
{
    const float* x    = (const float*)d_in[0];
    const float* h    = (const float*)d_in[1];
    const int*   ei   = (const int*)d_in[2];
    const float* We1  = (const float*)d_in[3];
    const float* be1  = (const float*)d_in[4];
    const float* We2  = (const float*)d_in[5];
    const float* be2  = (const float*)d_in[6];
    const float* Wc1  = (const float*)d_in[7];
    const float* bc1  = (const float*)d_in[8];
    const float* Wc2  = (const float*)d_in[9];
    const float* bc2  = (const float*)d_in[10];
    const float* Wn1  = (const float*)d_in[11];
    const float* bn1  = (const float*)d_in[12];
    const float* Wn2  = (const float*)d_in[13];
    const float* bn2  = (const float*)d_in[14];
    const float* gamma = (const float*)d_in[15];
    const float* beta  = (const float*)d_in[16];

    int n = in_sizes[0] / 3;       // 50000
    int E = in_sizes[2] / 2;       // 800000

    float* xout = (float*)d_out;              // [n,3]
    float* hout = xout + (size_t)n * 3;       // [n,128]

    zero_kernel<<<256, 256>>>(n);
    edge_kernel<<<(E + TE - 1) / TE, 128>>>(x, h, ei, E, n,
                                            We1, be1, We2, be2,
                                            Wc1, bc1, Wc2, bc2);
    node_kernel<<<(n + TN - 1) / TN, 128>>>(x, h, n, Wn1, bn1, Wn2, bn2,
                                            gamma, beta, xout, hout);
}

// round 4
// speedup vs baseline: 2.4613x; 1.8525x over previous
#include <cuda_runtime.h>

#define H 128
#define NMAX 50000
#define TP 8            // edge pairs per GROUP (16 edges/group)
#define GE (2*TP)       // edges per group
#define TE (2*GE)       // 32 edges per block (2 groups)
#define TNP 4           // node pairs per group
#define GN (2*TNP)      // 8 nodes per group
#define TN (2*GN)       // 16 nodes per block

// Scratch (no dynamic allocation allowed)
__device__ float g_agg[NMAX * H];
__device__ float g_dx[NMAX * 3];
__device__ float g_cnt[NMAX];
__device__ float g_P[NMAX * H];   // h @ We1[0:128]
__device__ float g_Q[NMAX * H];   // h @ We1[128:256]

typedef unsigned long long u64;

__device__ __forceinline__ void ffma2(u64 &acc, u64 a, u64 b) {
    asm("fma.rn.f32x2 %0, %1, %2, %0;" : "+l"(acc) : "l"(a), "l"(b));
}
__device__ __forceinline__ u64 pack2(float v) {
    u64 r; unsigned u = __float_as_uint(v);
    asm("mov.b64 %0, {%1, %1};" : "=l"(r) : "r"(u));
    return r;
}
__device__ __forceinline__ float2 unpack2(u64 v) {
    unsigned lo, hi;
    asm("mov.b64 {%0, %1}, %2;" : "=r"(lo), "=r"(hi) : "l"(v));
    return make_float2(__uint_as_float(lo), __uint_as_float(hi));
}
__device__ __forceinline__ float silu(float v) {
    return v / (1.0f + __expf(-v));
}
__device__ __forceinline__ float2 silu2(u64 v) {
    float2 f = unpack2(v);
    return make_float2(silu(f.x), silu(f.y));
}

__global__ void zero_kernel(int n) {
    int total = n * H + n * 3 + n;
    for (int i = blockIdx.x * blockDim.x + threadIdx.x; i < total;
         i += gridDim.x * blockDim.x) {
        if (i < n * H) g_agg[i] = 0.0f;
        else if (i < n * H + n * 3) g_dx[i - n * H] = 0.0f;
        else g_cnt[i - n * H - n * 3] = 0.0f;
    }
}

// ---------------------------------------------------------------------------
// PQ precompute: P = h @ We1[0:128,:], Q = h @ We1[128:256,:]
// 2 groups x 64 threads; thread owns cols t, t+64; 4 node-pairs per group.
// ---------------------------------------------------------------------------
__global__ __launch_bounds__(128) void pq_kernel(
    const float* __restrict__ h, const float* __restrict__ We1, int n)
{
    __shared__ float2 s_h[2][TNP][H];
    const int j = threadIdx.x;
    const int g = j >> 6;
    const int t = j & 63;
    const int c0 = t, c1 = t + 64;
    const int n0 = blockIdx.x * TN + g * GN;

    #pragma unroll
    for (int p = 0; p < TNP; p++) {
        int na = n0 + 2 * p, nb = na + 1;
        float a0 = 0.f, a1 = 0.f, b0 = 0.f, b1 = 0.f;
        if (na < n) { a0 = h[(long)na * H + c0]; a1 = h[(long)na * H + c1]; }
        if (nb < n) { b0 = h[(long)nb * H + c0]; b1 = h[(long)nb * H + c1]; }
        s_h[g][p][c0] = make_float2(a0, b0);
        s_h[g][p][c1] = make_float2(a1, b1);
    }
    __syncthreads();

    u64 accP0[TNP], accP1[TNP], accQ0[TNP], accQ1[TNP];
    #pragma unroll
    for (int p = 0; p < TNP; p++) {
        accP0[p] = 0; accP1[p] = 0; accQ0[p] = 0; accQ1[p] = 0;
    }

    #pragma unroll 2
    for (int kk = 0; kk < 32; kk++) {
        int k = kk * 4;
        u64 pa0 = pack2(We1[(k + 0) * H + c0]);
        u64 pa1 = pack2(We1[(k + 1) * H + c0]);
        u64 pa2 = pack2(We1[(k + 2) * H + c0]);
        u64 pa3 = pack2(We1[(k + 3) * H + c0]);
        u64 pb0 = pack2(We1[(k + 0) * H + c1]);
        u64 pb1 = pack2(We1[(k + 1) * H + c1]);
        u64 pb2 = pack2(We1[(k + 2) * H + c1]);
        u64 pb3 = pack2(We1[(k + 3) * H + c1]);
        u64 qa0 = pack2(We1[(128 + k + 0) * H + c0]);
        u64 qa1 = pack2(We1[(128 + k + 1) * H + c0]);
        u64 qa2 = pack2(We1[(128 + k + 2) * H + c0]);
        u64 qa3 = pack2(We1[(128 + k + 3) * H + c0]);
        u64 qb0 = pack2(We1[(128 + k + 0) * H + c1]);
        u64 qb1 = pack2(We1[(128 + k + 1) * H + c1]);
        u64 qb2 = pack2(We1[(128 + k + 2) * H + c1]);
        u64 qb3 = pack2(We1[(128 + k + 3) * H + c1]);
        #pragma unroll
        for (int p = 0; p < TNP; p++) {
            ulonglong2 A0 = *(const ulonglong2*)&s_h[g][p][k];
            ulonglong2 A1 = *(const ulonglong2*)&s_h[g][p][k + 2];
            ffma2(accP0[p], A0.x, pa0); ffma2(accP1[p], A0.x, pb0);
            ffma2(accQ0[p], A0.x, qa0); ffma2(accQ1[p], A0.x, qb0);
            ffma2(accP0[p], A0.y, pa1); ffma2(accP1[p], A0.y, pb1);
            ffma2(accQ0[p], A0.y, qa1); ffma2(accQ1[p], A0.y, qb1);
            ffma2(accP0[p], A1.x, pa2); ffma2(accP1[p], A1.x, pb2);
            ffma2(accQ0[p], A1.x, qa2); ffma2(accQ1[p], A1.x, qb2);
            ffma2(accP0[p], A1.y, pa3); ffma2(accP1[p], A1.y, pb3);
            ffma2(accQ0[p], A1.y, qa3); ffma2(accQ1[p], A1.y, qb3);
        }
    }

    #pragma unroll
    for (int p = 0; p < TNP; p++) {
        int na = n0 + 2 * p, nb = na + 1;
        float2 vP0 = unpack2(accP0[p]), vP1 = unpack2(accP1[p]);
        float2 vQ0 = unpack2(accQ0[p]), vQ1 = unpack2(accQ1[p]);
        if (na < n) {
            g_P[(long)na * H + c0] = vP0.x; g_P[(long)na * H + c1] = vP1.x;
            g_Q[(long)na * H + c0] = vQ0.x; g_Q[(long)na * H + c1] = vQ1.x;
        }
        if (nb < n) {
            g_P[(long)nb * H + c0] = vP0.y; g_P[(long)nb * H + c1] = vP1.y;
            g_Q[(long)nb * H + c0] = vQ0.y; g_Q[(long)nb * H + c1] = vQ1.y;
        }
    }
}

// ---------------------------------------------------------------------------
// Edge kernel: layer-1 is now elementwise silu(P[row]+Q[col]+d2*wl+be1).
// Then two 128x128 GEMMs (e2, c1), gate reduce, scatter.
// ---------------------------------------------------------------------------
__global__ __launch_bounds__(128) void edge_kernel(
    const float* __restrict__ x, const int* __restrict__ ei, int E, int n,
    const float* __restrict__ We1, const float* __restrict__ be1,
    const float* __restrict__ We2, const float* __restrict__ be2,
    const float* __restrict__ Wc1, const float* __restrict__ bc1,
    const float* __restrict__ Wc2, const float* __restrict__ bc2)
{
    __shared__ float2 s_f1[2][TP][H];
    __shared__ float2 s_f2[2][TP][H];
    __shared__ float2 s_g[2][TP][H];
    __shared__ float  s_rel[TE][3];
    __shared__ float  s_d2[TE];
    __shared__ int    s_row[TE];
    __shared__ int    s_col[TE];
    __shared__ float  s_gate[TE];
    __shared__ float  s_wc2[H];

    const int j = threadIdx.x;
    const int g = j >> 6;          // group 0/1
    const int t = j & 63;          // owns cols t, t+64
    const int c0 = t, c1 = t + 64;
    const long e0b = (long)blockIdx.x * TE;

    s_wc2[j] = Wc2[j];

    // Phase 0: per-edge scalars (32 edges, 1 thread each)
    if (j < TE) {
        long e = e0b + j;
        int r = -1, c = 0;
        float rx = 0.f, ry = 0.f, rz = 0.f, d2 = 0.f;
        if (e < E) {
            r = ei[e];
            c = ei[E + e];
            rx = x[r * 3 + 0] - x[c * 3 + 0];
            ry = x[r * 3 + 1] - x[c * 3 + 1];
            rz = x[r * 3 + 2] - x[c * 3 + 2];
            d2 = rx * rx + ry * ry + rz * rz;
        }
        s_row[j] = r; s_col[j] = c; s_d2[j] = d2;
        s_rel[j][0] = rx; s_rel[j][1] = ry; s_rel[j][2] = rz;
    }
    __syncthreads();

    // Phase 1: layer-1 elementwise from P/Q gathers
    {
        float wl0 = We1[256 * H + c0], wl1 = We1[256 * H + c1];
        float b0 = be1[c0], b1 = be1[c1];
        #pragma unroll
        for (int p = 0; p < TP; p++) {
            int ia = g * GE + 2 * p, ib = ia + 1;
            int ra = s_row[ia], rb = s_row[ib];
            int ca = s_col[ia], cb = s_col[ib];
            float d2a = s_d2[ia], d2b = s_d2[ib];
            float fa0 = 0.f, fa1 = 0.f, fb0 = 0.f, fb1 = 0.f;
            if (ra >= 0) {
                fa0 = silu(g_P[(long)ra * H + c0] + g_Q[(long)ca * H + c0] + d2a * wl0 + b0);
                fa1 = silu(g_P[(long)ra * H + c1] + g_Q[(long)ca * H + c1] + d2a * wl1 + b1);
            }
            if (rb >= 0) {
                fb0 = silu(g_P[(long)rb * H + c0] + g_Q[(long)cb * H + c0] + d2b * wl0 + b0);
                fb1 = silu(g_P[(long)rb * H + c1] + g_Q[(long)cb * H + c1] + d2b * wl1 + b1);
            }
            s_f1[g][p][c0] = make_float2(fa0, fb0);
            s_f1[g][p][c1] = make_float2(fa1, fb1);
        }
    }
    __syncthreads();

    u64 acc0[TP], acc1[TP];

    // ---- Layer e2: 128 -> 128 ----
    {
        u64 ba = pack2(be2[c0]), bb = pack2(be2[c1]);
        #pragma unroll
        for (int p = 0; p < TP; p++) { acc0[p] = ba; acc1[p] = bb; }
        #pragma unroll 2
        for (int kk = 0; kk < 32; kk++) {
            int k = kk * 4;
            u64 wa0 = pack2(We2[(k + 0) * H + c0]);
            u64 wa1 = pack2(We2[(k + 1) * H + c0]);
            u64 wa2 = pack2(We2[(k + 2) * H + c0]);
            u64 wa3 = pack2(We2[(k + 3) * H + c0]);
            u64 wb0 = pack2(We2[(k + 0) * H + c1]);
            u64 wb1 = pack2(We2[(k + 1) * H + c1]);
            u64 wb2 = pack2(We2[(k + 2) * H + c1]);
            u64 wb3 = pack2(We2[(k + 3) * H + c1]);
            #pragma unroll
            for (int p = 0; p < TP; p++) {
                ulonglong2 A0 = *(const ulonglong2*)&s_f1[g][p][k];
                ulonglong2 A1 = *(const ulonglong2*)&s_f1[g][p][k + 2];
                ffma2(acc0[p], A0.x, wa0); ffma2(acc1[p], A0.x, wb0);
                ffma2(acc0[p], A0.y, wa1); ffma2(acc1[p], A0.y, wb1);
                ffma2(acc0[p], A1.x, wa2); ffma2(acc1[p], A1.x, wb2);
                ffma2(acc0[p], A1.y, wa3); ffma2(acc1[p], A1.y, wb3);
            }
        }
        #pragma unroll
        for (int p = 0; p < TP; p++) {
            s_f2[g][p][c0] = silu2(acc0[p]);
            s_f2[g][p][c1] = silu2(acc1[p]);
        }
    }
    __syncthreads();

    // ---- Gate hidden: 128 -> 128 ----
    {
        u64 ba = pack2(bc1[c0]), bb = pack2(bc1[c1]);
        #pragma unroll
        for (int p = 0; p < TP; p++) { acc0[p] = ba; acc1[p] = bb; }
        #pragma unroll 2
        for (int kk = 0; kk < 32; kk++) {
            int k = kk * 4;
            u64 wa0 = pack2(Wc1[(k + 0) * H + c0]);
            u64 wa1 = pack2(Wc1[(k + 1) * H + c0]);
            u64 wa2 = pack2(Wc1[(k + 2) * H + c0]);
            u64 wa3 = pack2(Wc1[(k + 3) * H + c0]);
            u64 wb0 = pack2(Wc1[(k + 0) * H + c1]);
            u64 wb1 = pack2(Wc1[(k + 1) * H + c1]);
            u64 wb2 = pack2(Wc1[(k + 2) * H + c1]);
            u64 wb3 = pack2(Wc1[(k + 3) * H + c1]);
            #pragma unroll
            for (int p = 0; p < TP; p++) {
                ulonglong2 A0 = *(const ulonglong2*)&s_f2[g][p][k];
                ulonglong2 A1 = *(const ulonglong2*)&s_f2[g][p][k + 2];
                ffma2(acc0[p], A0.x, wa0); ffma2(acc1[p], A0.x, wb0);
                ffma2(acc0[p], A0.y, wa1); ffma2(acc1[p], A0.y, wb1);
                ffma2(acc0[p], A1.x, wa2); ffma2(acc1[p], A1.x, wb2);
                ffma2(acc0[p], A1.y, wa3); ffma2(acc1[p], A1.y, wb3);
            }
        }
        #pragma unroll
        for (int p = 0; p < TP; p++) {
            s_g[g][p][c0] = silu2(acc0[p]);
            s_g[g][p][c1] = silu2(acc1[p]);
        }
    }
    __syncthreads();

    // ---- Gate reduce: 128 -> 1 per edge (4 warps over 32 edges) ----
    {
        float bc2v = bc2[0];
        int wid = j >> 5, lane = j & 31;
        for (int e = wid; e < TE; e += 4) {
            int eg = e >> 4, pe = (e & 15) >> 1, hf = e & 1;
            const float* gp = (const float*)&s_g[eg][pe][0]; // col c at gp[2c+hf]
            float ps = gp[2 * lane + hf]        * s_wc2[lane]
                     + gp[2 * (lane + 32) + hf] * s_wc2[lane + 32]
                     + gp[2 * (lane + 64) + hf] * s_wc2[lane + 64]
                     + gp[2 * (lane + 96) + hf] * s_wc2[lane + 96];
            #pragma unroll
            for (int off = 16; off > 0; off >>= 1)
                ps += __shfl_down_sync(0xffffffffu, ps, off);
            if (lane == 0) s_gate[e] = ps + bc2v;
        }
    }
    __syncthreads();

    // ---- Scatter ----
    #pragma unroll
    for (int p = 0; p < TP; p++) {
        int r0 = s_row[g * GE + 2 * p], r1 = s_row[g * GE + 2 * p + 1];
        float2 fa = s_f2[g][p][c0];
        float2 fb = s_f2[g][p][c1];
        if (r0 >= 0) {
            atomicAdd(&g_agg[(long)r0 * H + c0], fa.x);
            atomicAdd(&g_agg[(long)r0 * H + c1], fb.x);
        }
        if (r1 >= 0) {
            atomicAdd(&g_agg[(long)r1 * H + c0], fa.y);
            atomicAdd(&g_agg[(long)r1 * H + c1], fb.y);
        }
    }
    {
        int e = j >> 2, c = j & 3;   // 128 threads cover 32 edges x 4
        int r = s_row[e];
        if (r >= 0) {
            if (c < 3) atomicAdd(&g_dx[r * 3 + c], s_rel[e][c] * s_gate[e]);
            else       atomicAdd(&g_cnt[r], 1.0f);
        }
    }
}

// ---------------------------------------------------------------------------
// Node kernel: same as R3.
// ---------------------------------------------------------------------------
__global__ __launch_bounds__(128) void node_kernel(
    const float* __restrict__ x, const float* __restrict__ h, int n,
    const float* __restrict__ Wn1, const float* __restrict__ bn1,
    const float* __restrict__ Wn2, const float* __restrict__ bn2,
    const float* __restrict__ gamma, const float* __restrict__ beta,
    float* __restrict__ xout, float* __restrict__ hout)
{
    __shared__ float2 s_in[2][TNP][2 * H];
    __shared__ float2 s_h1[2][TNP][H];
    __shared__ float  s_h2[TN][H];
    __shared__ float  s_mu[TN], s_rs[TN];

    const int j = threadIdx.x;
    const int g = j >> 6;
    const int t = j & 63;
    const int c0 = t, c1 = t + 64;
    const int n0 = blockIdx.x * TN + g * GN;

    #pragma unroll
    for (int p = 0; p < TNP; p++) {
        int na = n0 + 2 * p, nb = na + 1;
        float ha0 = 0.f, ha1 = 0.f, hb0 = 0.f, hb1 = 0.f;
        float aa0 = 0.f, aa1 = 0.f, ab0 = 0.f, ab1 = 0.f;
        if (na < n) {
            float c = g_cnt[na]; c = c < 1.0f ? 1.0f : c; float ic = 1.0f / c;
            ha0 = h[(long)na * H + c0]; ha1 = h[(long)na * H + c1];
            aa0 = g_agg[(long)na * H + c0] * ic; aa1 = g_agg[(long)na * H + c1] * ic;
        }
        if (nb < n) {
            float c = g_cnt[nb]; c = c < 1.0f ? 1.0f : c; float ic = 1.0f / c;
            hb0 = h[(long)nb * H + c0]; hb1 = h[(long)nb * H + c1];
            ab0 = g_agg[(long)nb * H + c0] * ic; ab1 = g_agg[(long)nb * H + c1] * ic;
        }
        s_in[g][p][c0]     = make_float2(ha0, hb0);
        s_in[g][p][c1]     = make_float2(ha1, hb1);
        s_in[g][p][H + c0] = make_float2(aa0, ab0);
        s_in[g][p][H + c1] = make_float2(aa1, ab1);
    }
    __syncthreads();

    u64 acc0[TNP], acc1[TNP];

    // ---- Layer n1: 256 -> 128 ----
    {
        u64 ba = pack2(bn1[c0]), bb = pack2(bn1[c1]);
        #pragma unroll
        for (int p = 0; p < TNP; p++) { acc0[p] = ba; acc1[p] = bb; }
        #pragma unroll 2
        for (int kk = 0; kk < 64; kk++) {
            int k = kk * 4;
            u64 wa0 = pack2(Wn1[(k + 0) * H + c0]);
            u64 wa1 = pack2(Wn1[(k + 1) * H + c0]);
            u64 wa2 = pack2(Wn1[(k + 2) * H + c0]);
            u64 wa3 = pack2(Wn1[(k + 3) * H + c0]);
            u64 wb0 = pack2(Wn1[(k + 0) * H + c1]);
            u64 wb1 = pack2(Wn1[(k + 1) * H + c1]);
            u64 wb2 = pack2(Wn1[(k + 2) * H + c1]);
            u64 wb3 = pack2(Wn1[(k + 3) * H + c1]);
            #pragma unroll
            for (int p = 0; p < TNP; p++) {
                ulonglong2 A0 = *(const ulonglong2*)&s_in[g][p][k];
                ulonglong2 A1 = *(const ulonglong2*)&s_in[g][p][k + 2];
                ffma2(acc0[p], A0.x, wa0); ffma2(acc1[p], A0.x, wb0);
                ffma2(acc0[p], A0.y, wa1); ffma2(acc1[p], A0.y, wb1);
                ffma2(acc0[p], A1.x, wa2); ffma2(acc1[p], A1.x, wb2);
                ffma2(acc0[p], A1.y, wa3); ffma2(acc1[p], A1.y, wb3);
            }
        }
        #pragma unroll
        for (int p = 0; p < TNP; p++) {
            s_h1[g][p][c0] = silu2(acc0[p]);
            s_h1[g][p][c1] = silu2(acc1[p]);
        }
    }
    __syncthreads();

    // ---- Layer n2: 128 -> 128, residual ----
    {
        u64 ba = pack2(bn2[c0]), bb = pack2(bn2[c1]);
        #pragma unroll
        for (int p = 0; p < TNP; p++) { acc0[p] = ba; acc1[p] = bb; }
        #pragma unroll 2
        for (int kk = 0; kk < 32; kk++) {
            int k = kk * 4;
            u64 wa0 = pack2(Wn2[(k + 0) * H + c0]);
            u64 wa1 = pack2(Wn2[(k + 1) * H + c0]);
            u64 wa2 = pack2(Wn2[(k + 2) * H + c0]);
            u64 wa3 = pack2(Wn2[(k + 3) * H + c0]);
            u64 wb0 = pack2(Wn2[(k + 0) * H + c1]);
            u64 wb1 = pack2(Wn2[(k + 1) * H + c1]);
            u64 wb2 = pack2(Wn2[(k + 2) * H + c1]);
            u64 wb3 = pack2(Wn2[(k + 3) * H + c1]);
            #pragma unroll
            for (int p = 0; p < TNP; p++) {
                ulonglong2 A0 = *(const ulonglong2*)&s_h1[g][p][k];
                ulonglong2 A1 = *(const ulonglong2*)&s_h1[g][p][k + 2];
                ffma2(acc0[p], A0.x, wa0); ffma2(acc1[p], A0.x, wb0);
                ffma2(acc0[p], A0.y, wa1); ffma2(acc1[p], A0.y, wb1);
                ffma2(acc0[p], A1.x, wa2); ffma2(acc1[p], A1.x, wb2);
                ffma2(acc0[p], A1.y, wa3); ffma2(acc1[p], A1.y, wb3);
            }
        }
        #pragma unroll
        for (int p = 0; p < TNP; p++) {
            int na = n0 + 2 * p, nb = na + 1;
            float2 va = unpack2(acc0[p]);
            float2 vb = unpack2(acc1[p]);
            float ha0 = (na < n) ? h[(long)na * H + c0] : 0.0f;
            float ha1 = (na < n) ? h[(long)na * H + c1] : 0.0f;
            float hb0 = (nb < n) ? h[(long)nb * H + c0] : 0.0f;
            float hb1 = (nb < n) ? h[(long)nb * H + c1] : 0.0f;
            int la = g * GN + 2 * p, lb = la + 1;
            s_h2[la][c0] = ha0 + va.x;
            s_h2[la][c1] = ha1 + vb.x;
            s_h2[lb][c0] = hb0 + va.y;
            s_h2[lb][c1] = hb1 + vb.y;
        }
    }
    __syncthreads();

    // ---- LayerNorm stats: 4 warps over 16 nodes ----
    {
        int wid = j >> 5, lane = j & 31;
        #pragma unroll
        for (int q = 0; q < 4; q++) {
            int e = wid * 4 + q;
            float v0 = s_h2[e][lane];
            float v1 = s_h2[e][lane + 32];
            float v2 = s_h2[e][lane + 64];
            float v3 = s_h2[e][lane + 96];
            float s  = v0 + v1 + v2 + v3;
            float ss = v0 * v0 + v1 * v1 + v2 * v2 + v3 * v3;
            #pragma unroll
            for (int off = 16; off > 0; off >>= 1) {
                s  += __shfl_down_sync(0xffffffffu, s, off);
                ss += __shfl_down_sync(0xffffffffu, ss, off);
            }
            if (lane == 0) {
                float mu = s * (1.0f / H);
                float var = ss * (1.0f / H) - mu * mu;
                s_mu[e] = mu;
                s_rs[e] = rsqrtf(var + 1e-5f);
            }
        }
    }
    __syncthreads();

    // ---- Normalize + SiLU + outputs ----
    const int nb0 = blockIdx.x * TN;
    float gj = gamma[j], bj = beta[j];
    #pragma unroll
    for (int e = 0; e < TN; e++) {
        int ng = nb0 + e;
        if (ng < n) {
            float v = (s_h2[e][j] - s_mu[e]) * s_rs[e] * gj + bj;
            hout[(long)ng * H + j] = silu(v);
            if (j < 3) {
                float c = g_cnt[ng]; c = c < 1.0f ? 1.0f : c;
                xout[ng * 3 + j] = x[ng * 3 + j] + g_dx[ng * 3 + j] / c;
            }
        }
    }
}

extern "C" void kernel_launch(void* const* d_in, const int* in_sizes, int n_in,
                              void* d_out, int out_size)
{
    const float* x    = (const float*)d_in[0];
    const float* h    = (const float*)d_in[1];
    const int*   ei   = (const int*)d_in[2];
    const float* We1  = (const float*)d_in[3];
    const float* be1  = (const float*)d_in[4];
    const float* We2  = (const float*)d_in[5];
    const float* be2  = (const float*)d_in[6];
    const float* Wc1  = (const float*)d_in[7];
    const float* bc1  = (const float*)d_in[8];
    const float* Wc2  = (const float*)d_in[9];
    const float* bc2  = (const float*)d_in[10];
    const float* Wn1  = (const float*)d_in[11];
    const float* bn1  = (const float*)d_in[12];
    const float* Wn2  = (const float*)d_in[13];
    const float* bn2  = (const float*)d_in[14];
    const float* gamma = (const float*)d_in[15];
    const float* beta  = (const float*)d_in[16];

    int n = in_sizes[0] / 3;       // 50000
    int E = in_sizes[2] / 2;       // 800000

    float* xout = (float*)d_out;              // [n,3]
    float* hout = xout + (size_t)n * 3;       // [n,128]

    zero_kernel<<<256, 256>>>(n);
    pq_kernel<<<(n + TN - 1) / TN, 128>>>(h, We1, n);
    edge_kernel<<<(E + TE - 1) / TE, 128>>>(x, ei, E, n,
                                            We1, be1, We2, be2,
                                            Wc1, bc1, Wc2, bc2);
    node_kernel<<<(n + TN - 1) / TN, 128>>>(x, h, n, Wn1, bn1, Wn2, bn2,
                                            gamma, beta, xout, hout);
}

// round 5
// speedup vs baseline: 4.0324x; 1.6383x over previous
#include <cuda_runtime.h>

#define H 128
#define NMAX 50000
#define TEK 32          // edges per block (edge kernel)
#define TNP 4           // node pairs per group
#define GN (2*TNP)
#define TN (2*GN)

// Scratch (no dynamic allocation allowed)
__device__ float g_agg[NMAX * H];
__device__ float g_dx[NMAX * 3];
__device__ float g_cnt[NMAX];
__device__ float g_P[NMAX * H];        // h @ We1[0:128]
__device__ float g_Q[NMAX * H];        // h @ We1[128:256]
__device__ float g_W2e[16 * 16 * 32 * 2];  // We2 fragment-swizzled tf32
__device__ float g_W2c[16 * 16 * 32 * 2];  // Wc1 fragment-swizzled tf32

typedef unsigned long long u64;

__device__ __forceinline__ void ffma2(u64 &acc, u64 a, u64 b) {
    asm("fma.rn.f32x2 %0, %1, %2, %0;" : "+l"(acc) : "l"(a), "l"(b));
}
__device__ __forceinline__ u64 pack2(float v) {
    u64 r; unsigned u = __float_as_uint(v);
    asm("mov.b64 %0, {%1, %1};" : "=l"(r) : "r"(u));
    return r;
}
__device__ __forceinline__ float2 unpack2(u64 v) {
    unsigned lo, hi;
    asm("mov.b64 {%0, %1}, %2;" : "=r"(lo), "=r"(hi) : "l"(v));
    return make_float2(__uint_as_float(lo), __uint_as_float(hi));
}
__device__ __forceinline__ float silu(float v) {
    return v / (1.0f + __expf(-v));
}
__device__ __forceinline__ float2 silu2(u64 v) {
    float2 f = unpack2(v);
    return make_float2(silu(f.x), silu(f.y));
}
__device__ __forceinline__ unsigned tf32u(float f) {
    unsigned r; asm("cvt.rna.tf32.f32 %0, %1;" : "=r"(r) : "f"(f));
    return r;
}
__device__ __forceinline__ float tf32f(float f) {
    return __uint_as_float(tf32u(f));
}
__device__ __forceinline__ void mma_tf32(float c[4],
    unsigned a0, unsigned a1, unsigned a2, unsigned a3,
    unsigned b0, unsigned b1)
{
    asm("mma.sync.aligned.m16n8k8.row.col.f32.tf32.tf32.f32 "
        "{%0,%1,%2,%3},{%4,%5,%6,%7},{%8,%9},{%0,%1,%2,%3};"
        : "+f"(c[0]), "+f"(c[1]), "+f"(c[2]), "+f"(c[3])
        : "r"(a0), "r"(a1), "r"(a2), "r"(a3), "r"(b0), "r"(b1));
}

__global__ void zero_kernel(int n) {
    int total = n * H + n * 3 + n;
    for (int i = blockIdx.x * blockDim.x + threadIdx.x; i < total;
         i += gridDim.x * blockDim.x) {
        if (i < n * H) g_agg[i] = 0.0f;
        else if (i < n * H + n * 3) g_dx[i - n * H] = 0.0f;
        else g_cnt[i - n * H - n * 3] = 0.0f;
    }
}

// Fragment-swizzle We2 and Wc1 into tf32 B-frag order:
// g_W2*[((tp*16+s)*32+lane)*2 + r] = tf32(W[8s + tg + 4r][8tp + g])
__global__ void prep_kernel(const float* __restrict__ We2,
                            const float* __restrict__ Wc1)
{
    int i = blockIdx.x * blockDim.x + threadIdx.x;
    if (i >= 16 * 16 * 32 * 2) return;
    int r    = i & 1;
    int lane = (i >> 1) & 31;
    int s    = (i >> 6) & 15;
    int tp   = i >> 10;
    int g = lane >> 2, tg = lane & 3;
    int k = 8 * s + tg + 4 * r;
    int n = 8 * tp + g;
    g_W2e[i] = tf32f(We2[k * H + n]);
    g_W2c[i] = tf32f(Wc1[k * H + n]);
}

// ---------------------------------------------------------------------------
// PQ precompute: P = h @ We1[0:128,:], Q = h @ We1[128:256,:]  (f32x2 path)
// ---------------------------------------------------------------------------
__global__ __launch_bounds__(128) void pq_kernel(
    const float* __restrict__ h, const float* __restrict__ We1, int n)
{
    __shared__ float2 s_h[2][TNP][H];
    const int j = threadIdx.x;
    const int g = j >> 6;
    const int t = j & 63;
    const int c0 = t, c1 = t + 64;
    const int n0 = blockIdx.x * TN + g * GN;

    #pragma unroll
    for (int p = 0; p < TNP; p++) {
        int na = n0 + 2 * p, nb = na + 1;
        float a0 = 0.f, a1 = 0.f, b0 = 0.f, b1 = 0.f;
        if (na < n) { a0 = h[(long)na * H + c0]; a1 = h[(long)na * H + c1]; }
        if (nb < n) { b0 = h[(long)nb * H + c0]; b1 = h[(long)nb * H + c1]; }
        s_h[g][p][c0] = make_float2(a0, b0);
        s_h[g][p][c1] = make_float2(a1, b1);
    }
    __syncthreads();

    u64 accP0[TNP], accP1[TNP], accQ0[TNP], accQ1[TNP];
    #pragma unroll
    for (int p = 0; p < TNP; p++) {
        accP0[p] = 0; accP1[p] = 0; accQ0[p] = 0; accQ1[p] = 0;
    }

    #pragma unroll 2
    for (int kk = 0; kk < 32; kk++) {
        int k = kk * 4;
        u64 pa0 = pack2(We1[(k + 0) * H + c0]);
        u64 pa1 = pack2(We1[(k + 1) * H + c0]);
        u64 pa2 = pack2(We1[(k + 2) * H + c0]);
        u64 pa3 = pack2(We1[(k + 3) * H + c0]);
        u64 pb0 = pack2(We1[(k + 0) * H + c1]);
        u64 pb1 = pack2(We1[(k + 1) * H + c1]);
        u64 pb2 = pack2(We1[(k + 2) * H + c1]);
        u64 pb3 = pack2(We1[(k + 3) * H + c1]);
        u64 qa0 = pack2(We1[(128 + k + 0) * H + c0]);
        u64 qa1 = pack2(We1[(128 + k + 1) * H + c0]);
        u64 qa2 = pack2(We1[(128 + k + 2) * H + c0]);
        u64 qa3 = pack2(We1[(128 + k + 3) * H + c0]);
        u64 qb0 = pack2(We1[(128 + k + 0) * H + c1]);
        u64 qb1 = pack2(We1[(128 + k + 1) * H + c1]);
        u64 qb2 = pack2(We1[(128 + k + 2) * H + c1]);
        u64 qb3 = pack2(We1[(128 + k + 3) * H + c1]);
        #pragma unroll
        for (int p = 0; p < TNP; p++) {
            ulonglong2 A0 = *(const ulonglong2*)&s_h[g][p][k];
            ulonglong2 A1 = *(const ulonglong2*)&s_h[g][p][k + 2];
            ffma2(accP0[p], A0.x, pa0); ffma2(accP1[p], A0.x, pb0);
            ffma2(accQ0[p], A0.x, qa0); ffma2(accQ1[p], A0.x, qb0);
            ffma2(accP0[p], A0.y, pa1); ffma2(accP1[p], A0.y, pb1);
            ffma2(accQ0[p], A0.y, qa1); ffma2(accQ1[p], A0.y, qb1);
            ffma2(accP0[p], A1.x, pa2); ffma2(accP1[p], A1.x, pb2);
            ffma2(accQ0[p], A1.x, qa2); ffma2(accQ1[p], A1.x, qb2);
            ffma2(accP0[p], A1.y, pa3); ffma2(accP1[p], A1.y, pb3);
            ffma2(accQ0[p], A1.y, qa3); ffma2(accQ1[p], A1.y, qb3);
        }
    }

    #pragma unroll
    for (int p = 0; p < TNP; p++) {
        int na = n0 + 2 * p, nb = na + 1;
        float2 vP0 = unpack2(accP0[p]), vP1 = unpack2(accP1[p]);
        float2 vQ0 = unpack2(accQ0[p]), vQ1 = unpack2(accQ1[p]);
        if (na < n) {
            g_P[(long)na * H + c0] = vP0.x; g_P[(long)na * H + c1] = vP1.x;
            g_Q[(long)na * H + c0] = vQ0.x; g_Q[(long)na * H + c1] = vQ1.x;
        }
        if (nb < n) {
            g_P[(long)nb * H + c0] = vP0.y; g_P[(long)nb * H + c1] = vP1.y;
            g_Q[(long)nb * H + c0] = vQ0.y; g_Q[(long)nb * H + c1] = vQ1.y;
        }
    }
}

// ---------------------------------------------------------------------------
// Edge kernel: layer-1 elementwise (exact fp32), then two tf32 tensor GEMMs.
// 4 warps; warp w owns output cols [32w, 32w+32); M=32 edges; K=128.
// ---------------------------------------------------------------------------
__global__ __launch_bounds__(128) void edge_kernel(
    const float* __restrict__ x, const int* __restrict__ ei, int E,
    const float* __restrict__ We1, const float* __restrict__ be1,
    const float* __restrict__ be2, const float* __restrict__ bc1,
    const float* __restrict__ Wc2, const float* __restrict__ bc2)
{
    __shared__ float s_f1[TEK][132];
    __shared__ float s_f2[TEK][132];
    __shared__ float s_rel[TEK][3];
    __shared__ float s_d2[TEK];
    __shared__ int   s_row[TEK], s_col[TEK];
    __shared__ float s_gp[4][TEK];
    __shared__ float s_gate[TEK];

    const int j = threadIdx.x;
    const int w = j >> 5, lane = j & 31;
    const int g = lane >> 2, tg = lane & 3;
    const long e0 = (long)blockIdx.x * TEK;

    // Phase 0: per-edge scalars
    if (j < TEK) {
        long e = e0 + j;
        int r = -1, c = 0;
        float rx = 0.f, ry = 0.f, rz = 0.f, d2 = 0.f;
        if (e < E) {
            r = ei[e]; c = ei[E + e];
            rx = x[r * 3 + 0] - x[c * 3 + 0];
            ry = x[r * 3 + 1] - x[c * 3 + 1];
            rz = x[r * 3 + 2] - x[c * 3 + 2];
            d2 = rx * rx + ry * ry + rz * rz;
        }
        s_row[j] = r; s_col[j] = c; s_d2[j] = d2;
        s_rel[j][0] = rx; s_rel[j][1] = ry; s_rel[j][2] = rz;
    }
    __syncthreads();

    // Phase 1: layer-1 elementwise (thread j = column j)
    {
        float wl = We1[256 * H + j];
        float b  = be1[j];
        #pragma unroll 4
        for (int e = 0; e < TEK; e++) {
            int r = s_row[e], c = s_col[e];
            float v = 0.f;
            if (r >= 0)
                v = silu(g_P[(long)r * H + j] + g_Q[(long)c * H + j]
                         + s_d2[e] * wl + b);
            s_f1[e][j] = v;
        }
    }
    __syncthreads();

    float cc[4][2][4];

    // ---- GEMM1: f2 = silu(f1 @ We2 + be2), tf32 tensor ----
    #pragma unroll
    for (int t = 0; t < 4; t++)
        #pragma unroll
        for (int mt = 0; mt < 2; mt++)
            #pragma unroll
            for (int q = 0; q < 4; q++) cc[t][mt][q] = 0.f;

    #pragma unroll 4
    for (int s = 0; s < 16; s++) {
        int k = 8 * s;
        unsigned a00 = tf32u(s_f1[g     ][k + tg]);
        unsigned a01 = tf32u(s_f1[g + 8 ][k + tg]);
        unsigned a02 = tf32u(s_f1[g     ][k + tg + 4]);
        unsigned a03 = tf32u(s_f1[g + 8 ][k + tg + 4]);
        unsigned a10 = tf32u(s_f1[g + 16][k + tg]);
        unsigned a11 = tf32u(s_f1[g + 24][k + tg]);
        unsigned a12 = tf32u(s_f1[g + 16][k + tg + 4]);
        unsigned a13 = tf32u(s_f1[g + 24][k + tg + 4]);
        #pragma unroll
        for (int t = 0; t < 4; t++) {
            float2 bv = *(const float2*)&g_W2e[((((4 * w + t) * 16 + s) * 32 + lane)) * 2];
            unsigned b0 = __float_as_uint(bv.x), b1 = __float_as_uint(bv.y);
            mma_tf32(cc[t][0], a00, a01, a02, a03, b0, b1);
            mma_tf32(cc[t][1], a10, a11, a12, a13, b0, b1);
        }
    }
    // epilogue: silu + bias -> s_f2 (full fp32 kept for scatter)
    #pragma unroll
    for (int t = 0; t < 4; t++) {
        int col = 32 * w + 8 * t + 2 * tg;
        float b0 = be2[col], b1 = be2[col + 1];
        #pragma unroll
        for (int mt = 0; mt < 2; mt++) {
            int r0 = g + 16 * mt, r1 = r0 + 8;
            s_f2[r0][col]     = silu(cc[t][mt][0] + b0);
            s_f2[r0][col + 1] = silu(cc[t][mt][1] + b1);
            s_f2[r1][col]     = silu(cc[t][mt][2] + b0);
            s_f2[r1][col + 1] = silu(cc[t][mt][3] + b1);
        }
    }
    __syncthreads();

    // ---- GEMM2: gate hidden = silu(f2 @ Wc1 + bc1), consumed in registers ----
    #pragma unroll
    for (int t = 0; t < 4; t++)
        #pragma unroll
        for (int mt = 0; mt < 2; mt++)
            #pragma unroll
            for (int q = 0; q < 4; q++) cc[t][mt][q] = 0.f;

    #pragma unroll 4
    for (int s = 0; s < 16; s++) {
        int k = 8 * s;
        unsigned a00 = tf32u(s_f2[g     ][k + tg]);
        unsigned a01 = tf32u(s_f2[g + 8 ][k + tg]);
        unsigned a02 = tf32u(s_f2[g     ][k + tg + 4]);
        unsigned a03 = tf32u(s_f2[g + 8 ][k + tg + 4]);
        unsigned a10 = tf32u(s_f2[g + 16][k + tg]);
        unsigned a11 = tf32u(s_f2[g + 24][k + tg]);
        unsigned a12 = tf32u(s_f2[g + 16][k + tg + 4]);
        unsigned a13 = tf32u(s_f2[g + 24][k + tg + 4]);
        #pragma unroll
        for (int t = 0; t < 4; t++) {
            float2 bv = *(const float2*)&g_W2c[((((4 * w + t) * 16 + s) * 32 + lane)) * 2];
            unsigned b0 = __float_as_uint(bv.x), b1 = __float_as_uint(bv.y);
            mma_tf32(cc[t][0], a00, a01, a02, a03, b0, b1);
            mma_tf32(cc[t][1], a10, a11, a12, a13, b0, b1);
        }
    }
    // gate partial dot with Wc2, per thread covers edge rows g, g+8, g+16, g+24
    {
        float p0 = 0.f, p1 = 0.f, p2 = 0.f, p3 = 0.f;
        #pragma unroll
        for (int t = 0; t < 4; t++) {
            int col = 32 * w + 8 * t + 2 * tg;
            float w0 = Wc2[col], w1 = Wc2[col + 1];
            float b0 = bc1[col], b1 = bc1[col + 1];
            p0 += silu(cc[t][0][0] + b0) * w0 + silu(cc[t][0][1] + b1) * w1;
            p1 += silu(cc[t][0][2] + b0) * w0 + silu(cc[t][0][3] + b1) * w1;
            p2 += silu(cc[t][1][0] + b0) * w0 + silu(cc[t][1][1] + b1) * w1;
            p3 += silu(cc[t][1][2] + b0) * w0 + silu(cc[t][1][3] + b1) * w1;
        }
        p0 += __shfl_xor_sync(0xffffffffu, p0, 1);
        p0 += __shfl_xor_sync(0xffffffffu, p0, 2);
        p1 += __shfl_xor_sync(0xffffffffu, p1, 1);
        p1 += __shfl_xor_sync(0xffffffffu, p1, 2);
        p2 += __shfl_xor_sync(0xffffffffu, p2, 1);
        p2 += __shfl_xor_sync(0xffffffffu, p2, 2);
        p3 += __shfl_xor_sync(0xffffffffu, p3, 1);
        p3 += __shfl_xor_sync(0xffffffffu, p3, 2);
        if (tg == 0) {
            s_gp[w][g]      = p0;
            s_gp[w][g + 8]  = p1;
            s_gp[w][g + 16] = p2;
            s_gp[w][g + 24] = p3;
        }
    }
    __syncthreads();

    if (j < TEK)
        s_gate[j] = s_gp[0][j] + s_gp[1][j] + s_gp[2][j] + s_gp[3][j] + bc2[0];

    // agg scatter (thread j = column j)
    #pragma unroll 4
    for (int e = 0; e < TEK; e++) {
        int r = s_row[e];
        if (r >= 0) atomicAdd(&g_agg[(long)r * H + j], s_f2[e][j]);
    }
    __syncthreads();

    {
        int e = j >> 2, c = j & 3;    // 128 threads = 32 edges x 4
        int r = s_row[e];
        if (r >= 0) {
            if (c < 3) atomicAdd(&g_dx[r * 3 + c], s_rel[e][c] * s_gate[e]);
            else       atomicAdd(&g_cnt[r], 1.0f);
        }
    }
}

// ---------------------------------------------------------------------------
// Node kernel (unchanged from R4)
// ---------------------------------------------------------------------------
__global__ __launch_bounds__(128) void node_kernel(
    const float* __restrict__ x, const float* __restrict__ h, int n,
    const float* __restrict__ Wn1, const float* __restrict__ bn1,
    const float* __restrict__ Wn2, const float* __restrict__ bn2,
    const float* __restrict__ gamma, const float* __restrict__ beta,
    float* __restrict__ xout, float* __restrict__ hout)
{
    __shared__ float2 s_in[2][TNP][2 * H];
    __shared__ float2 s_h1[2][TNP][H];
    __shared__ float  s_h2[TN][H];
    __shared__ float  s_mu[TN], s_rs[TN];

    const int j = threadIdx.x;
    const int g = j >> 6;
    const int t = j & 63;
    const int c0 = t, c1 = t + 64;
    const int n0 = blockIdx.x * TN + g * GN;

    #pragma unroll
    for (int p = 0; p < TNP; p++) {
        int na = n0 + 2 * p, nb = na + 1;
        float ha0 = 0.f, ha1 = 0.f, hb0 = 0.f, hb1 = 0.f;
        float aa0 = 0.f, aa1 = 0.f, ab0 = 0.f, ab1 = 0.f;
        if (na < n) {
            float c = g_cnt[na]; c = c < 1.0f ? 1.0f : c; float ic = 1.0f / c;
            ha0 = h[(long)na * H + c0]; ha1 = h[(long)na * H + c1];
            aa0 = g_agg[(long)na * H + c0] * ic; aa1 = g_agg[(long)na * H + c1] * ic;
        }
        if (nb < n) {
            float c = g_cnt[nb]; c = c < 1.0f ? 1.0f : c; float ic = 1.0f / c;
            hb0 = h[(long)nb * H + c0]; hb1 = h[(long)nb * H + c1];
            ab0 = g_agg[(long)nb * H + c0] * ic; ab1 = g_agg[(long)nb * H + c1] * ic;
        }
        s_in[g][p][c0]     = make_float2(ha0, hb0);
        s_in[g][p][c1]     = make_float2(ha1, hb1);
        s_in[g][p][H + c0] = make_float2(aa0, ab0);
        s_in[g][p][H + c1] = make_float2(aa1, ab1);
    }
    __syncthreads();

    u64 acc0[TNP], acc1[TNP];

    // ---- Layer n1: 256 -> 128 ----
    {
        u64 ba = pack2(bn1[c0]), bb = pack2(bn1[c1]);
        #pragma unroll
        for (int p = 0; p < TNP; p++) { acc0[p] = ba; acc1[p] = bb; }
        #pragma unroll 2
        for (int kk = 0; kk < 64; kk++) {
            int k = kk * 4;
            u64 wa0 = pack2(Wn1[(k + 0) * H + c0]);
            u64 wa1 = pack2(Wn1[(k + 1) * H + c0]);
            u64 wa2 = pack2(Wn1[(k + 2) * H + c0]);
            u64 wa3 = pack2(Wn1[(k + 3) * H + c0]);
            u64 wb0 = pack2(Wn1[(k + 0) * H + c1]);
            u64 wb1 = pack2(Wn1[(k + 1) * H + c1]);
            u64 wb2 = pack2(Wn1[(k + 2) * H + c1]);
            u64 wb3 = pack2(Wn1[(k + 3) * H + c1]);
            #pragma unroll
            for (int p = 0; p < TNP; p++) {
                ulonglong2 A0 = *(const ulonglong2*)&s_in[g][p][k];
                ulonglong2 A1 = *(const ulonglong2*)&s_in[g][p][k + 2];
                ffma2(acc0[p], A0.x, wa0); ffma2(acc1[p], A0.x, wb0);
                ffma2(acc0[p], A0.y, wa1); ffma2(acc1[p], A0.y, wb1);
                ffma2(acc0[p], A1.x, wa2); ffma2(acc1[p], A1.x, wb2);
                ffma2(acc0[p], A1.y, wa3); ffma2(acc1[p], A1.y, wb3);
            }
        }
        #pragma unroll
        for (int p = 0; p < TNP; p++) {
            s_h1[g][p][c0] = silu2(acc0[p]);
            s_h1[g][p][c1] = silu2(acc1[p]);
        }
    }
    __syncthreads();

    // ---- Layer n2: 128 -> 128, residual ----
    {
        u64 ba = pack2(bn2[c0]), bb = pack2(bn2[c1]);
        #pragma unroll
        for (int p = 0; p < TNP; p++) { acc0[p] = ba; acc1[p] = bb; }
        #pragma unroll 2
        for (int kk = 0; kk < 32; kk++) {
            int k = kk * 4;
            u64 wa0 = pack2(Wn2[(k + 0) * H + c0]);
            u64 wa1 = pack2(Wn2[(k + 1) * H + c0]);
            u64 wa2 = pack2(Wn2[(k + 2) * H + c0]);
            u64 wa3 = pack2(Wn2[(k + 3) * H + c0]);
            u64 wb0 = pack2(Wn2[(k + 0) * H + c1]);
            u64 wb1 = pack2(Wn2[(k + 1) * H + c1]);
            u64 wb2 = pack2(Wn2[(k + 2) * H + c1]);
            u64 wb3 = pack2(Wn2[(k + 3) * H + c1]);
            #pragma unroll
            for (int p = 0; p < TNP; p++) {
                ulonglong2 A0 = *(const ulonglong2*)&s_h1[g][p][k];
                ulonglong2 A1 = *(const ulonglong2*)&s_h1[g][p][k + 2];
                ffma2(acc0[p], A0.x, wa0); ffma2(acc1[p], A0.x, wb0);
                ffma2(acc0[p], A0.y, wa1); ffma2(acc1[p], A0.y, wb1);
                ffma2(acc0[p], A1.x, wa2); ffma2(acc1[p], A1.x, wb2);
                ffma2(acc0[p], A1.y, wa3); ffma2(acc1[p], A1.y, wb3);
            }
        }
        #pragma unroll
        for (int p = 0; p < TNP; p++) {
            int na = n0 + 2 * p, nb = na + 1;
            float2 va = unpack2(acc0[p]);
            float2 vb = unpack2(acc1[p]);
            float ha0 = (na < n) ? h[(long)na * H + c0] : 0.0f;
            float ha1 = (na < n) ? h[(long)na * H + c1] : 0.0f;
            float hb0 = (nb < n) ? h[(long)nb * H + c0] : 0.0f;
            float hb1 = (nb < n) ? h[(long)nb * H + c1] : 0.0f;
            int la = g * GN + 2 * p, lb = la + 1;
            s_h2[la][c0] = ha0 + va.x;
            s_h2[la][c1] = ha1 + vb.x;
            s_h2[lb][c0] = hb0 + va.y;
            s_h2[lb][c1] = hb1 + vb.y;
        }
    }
    __syncthreads();

    // ---- LayerNorm stats ----
    {
        int wid = j >> 5, lane = j & 31;
        #pragma unroll
        for (int q = 0; q < 4; q++) {
            int e = wid * 4 + q;
            float v0 = s_h2[e][lane];
            float v1 = s_h2[e][lane + 32];
            float v2 = s_h2[e][lane + 64];
            float v3 = s_h2[e][lane + 96];
            float s  = v0 + v1 + v2 + v3;
            float ss = v0 * v0 + v1 * v1 + v2 * v2 + v3 * v3;
            #pragma unroll
            for (int off = 16; off > 0; off >>= 1) {
                s  += __shfl_down_sync(0xffffffffu, s, off);
                ss += __shfl_down_sync(0xffffffffu, ss, off);
            }
            if (lane == 0) {
                float mu = s * (1.0f / H);
                float var = ss * (1.0f / H) - mu * mu;
                s_mu[e] = mu;
                s_rs[e] = rsqrtf(var + 1e-5f);
            }
        }
    }
    __syncthreads();

    // ---- Normalize + SiLU + outputs ----
    const int nb0 = blockIdx.x * TN;
    float gj = gamma[j], bj = beta[j];
    #pragma unroll
    for (int e = 0; e < TN; e++) {
        int ng = nb0 + e;
        if (ng < n) {
            float v = (s_h2[e][j] - s_mu[e]) * s_rs[e] * gj + bj;
            hout[(long)ng * H + j] = silu(v);
            if (j < 3) {
                float c = g_cnt[ng]; c = c < 1.0f ? 1.0f : c;
                xout[ng * 3 + j] = x[ng * 3 + j] + g_dx[ng * 3 + j] / c;
            }
        }
    }
}

extern "C" void kernel_launch(void* const* d_in, const int* in_sizes, int n_in,
                              void* d_out, int out_size)
{
    const float* x    = (const float*)d_in[0];
    const float* h    = (const float*)d_in[1];
    const int*   ei   = (const int*)d_in[2];
    const float* We1  = (const float*)d_in[3];
    const float* be1  = (const float*)d_in[4];
    const float* We2  = (const float*)d_in[5];
    const float* be2  = (const float*)d_in[6];
    const float* Wc1  = (const float*)d_in[7];
    const float* bc1  = (const float*)d_in[8];
    const float* Wc2  = (const float*)d_in[9];
    const float* bc2  = (const float*)d_in[10];
    const float* Wn1  = (const float*)d_in[11];
    const float* bn1  = (const float*)d_in[12];
    const float* Wn2  = (const float*)d_in[13];
    const float* bn2  = (const float*)d_in[14];
    const float* gamma = (const float*)d_in[15];
    const float* beta  = (const float*)d_in[16];

    int n = in_sizes[0] / 3;       // 50000
    int E = in_sizes[2] / 2;       // 800000

    float* xout = (float*)d_out;              // [n,3]
    float* hout = xout + (size_t)n * 3;       // [n,128]

    zero_kernel<<<256, 256>>>(n);
    prep_kernel<<<32, 512>>>(We2, Wc1);
    pq_kernel<<<(n + TN - 1) / TN, 128>>>(h, We1, n);
    edge_kernel<<<(E + TEK - 1) / TEK, 128>>>(x, ei, E,
                                              We1, be1, be2, bc1, Wc2, bc2);
    node_kernel<<<(n + TN - 1) / TN, 128>>>(x, h, n, Wn1, bn1, Wn2, bn2,
                                            gamma, beta, xout, hout);
}